// round 4
// baseline (speedup 1.0000x reference)
#include <cuda_runtime.h>
#include <cuda_bf16.h>
#include <math.h>

// ---------------- problem constants ----------------
#define LN      256
#define MEMD    256
#define IND     300
#define MTOT    511
#define HIDD    128
#define NCLS    5
#define NBLK    296

// ---------------- device scratch ----------------
__device__ float  g_WxT[IND * 768];
__device__ float4 g_Wpack[MEMD * MEMD];
__device__ float  g_W1T[MEMD * MEMD];
__device__ float  g_W2T[MEMD * MEMD];
__device__ float  g_iou[512 * 768];
__device__ float  g_mat[2][MTOT * MEMD];
__device__ float  g_c  [2][MTOT * MEMD];
__device__ float  g_pb [2][MTOT * MEMD];
__device__ float  g_colsum[2][MEMD];
__device__ float  g_hA [2][MTOT * MEMD];
__device__ float  g_cA [2][MTOT * MEMD];
__device__ float  g_hPre[2][MTOT * MEMD];
__device__ float  g_scores[2][MTOT * MTOT];
__device__ int    g_bar[64];

__device__ __forceinline__ float sigm_acc(float x) { return 1.0f / (1.0f + expf(-x)); }
__device__ __forceinline__ float tanh_fast(float x) {
    float y; asm("tanh.approx.f32 %0, %1;" : "=f"(y) : "f"(x)); return y;
}

// ---------------- global software barrier ----------------
__device__ __forceinline__ void gbar(int id) {
    __syncthreads();
    if (threadIdx.x == 0) {
        __threadfence();
        atomicAdd(&g_bar[id], 1);
        while (*((volatile int*)&g_bar[id]) < NBLK) { }
        __threadfence();
    }
    __syncthreads();
}

__global__ void reset_kernel() {
    if (threadIdx.x < 64) g_bar[threadIdx.x] = 0;
}

// ================= stages =================

__device__ void st_prep(int bid, int tid,
                        const float* __restrict__ W_ioux, const float* __restrict__ W_iouh,
                        const float* __restrict__ W_fh,   const float* __restrict__ W_attnh) {
    const int N1 = IND * 768, N2 = MEMD * MEMD, N3 = MEMD * MEMD, N4 = MEMD * MEMD;
    for (int i = bid * 256 + tid; i < N1 + N2 + N3 + N4; i += NBLK * 256) {
        if (i < N1) {
            int t = i / 768, j = i - t * 768;
            g_WxT[i] = W_ioux[j * IND + t];
        } else if (i < N1 + N2) {
            int e = i - N1; int t = e >> 8, j = e & 255;
            g_Wpack[e] = make_float4(W_iouh[j * MEMD + t],
                                     W_iouh[(256 + j) * MEMD + t],
                                     W_iouh[(512 + j) * MEMD + t],
                                     W_fh[j * MEMD + t]);
        } else if (i < N1 + N2 + N3) {
            int e = i - N1 - N2; int ee = e >> 8, d = e & 255;
            g_W1T[e] = W_attnh[d * 512 + ee];
        } else {
            int e = i - N1 - N2 - N3; int ee = e >> 8, d = e & 255;
            g_W2T[e] = W_attnh[d * 512 + 256 + ee];
        }
    }
}

// leaf GEMM: 192 blocks = 64 row-groups (8 rows) x 3 col-parts (256 cols)
__device__ void st_leafgemm(int bid, int tid, char* sm,
                            const int* __restrict__ l_idx, const int* __restrict__ r_idx,
                            const float* __restrict__ emb,
                            const float* __restrict__ b_ioux, const float* __restrict__ b_iouh) {
    if (bid >= 192) return;
    float* xs = (float*)sm;                 // 8*300
    int* sidx = (int*)(sm + 2400 * 4);      // 8 ints
    int rowgrp = bid & 63;
    int part = bid >> 6;
    if (tid < 8) {
        int grow = rowgrp * 8 + tid;
        sidx[tid] = (grow >= 256) ? r_idx[grow - 256] : l_idx[grow];
    }
    __syncthreads();
    for (int e = tid; e < 8 * IND; e += 256) {
        int rr = e / IND, t = e - rr * IND;
        xs[e] = emb[(long)sidx[rr] * IND + t];
    }
    __syncthreads();
    int col = part * 256 + tid;
    float bias = b_ioux[col] + b_iouh[col];
    float acc[8];
#pragma unroll
    for (int r = 0; r < 8; r++) acc[r] = bias;
#pragma unroll 4
    for (int t = 0; t < IND; t++) {
        float w = g_WxT[t * 768 + col];
#pragma unroll
        for (int r = 0; r < 8; r++) acc[r] = fmaf(w, xs[r * IND + t], acc[r]);
    }
#pragma unroll
    for (int r = 0; r < 8; r++) g_iou[(rowgrp * 8 + r) * 768 + col] = acc[r];
}

__device__ void st_leafgate(int bid, int tid) {
    for (int row = bid; row < 512; row += NBLK) {
        int side = row >> 8, leaf = row & 255;
        const float* base = g_iou + row * 768;
        float iv = sigm_acc(base[tid]);
        float ov = sigm_acc(base[256 + tid]);
        float uv = tanhf(base[512 + tid]);
        float c = iv * uv;
        float h = ov * tanhf(c);
        g_c[side][leaf * MEMD + tid]   = c;
        g_mat[side][leaf * MEMD + tid] = h;
    }
}

// tree level (mode 0: no-attn sides; mode 1: attended passes)
__device__ void st_tree(int bid, int tid, char* sm, int mode, int lev,
                        int offp, int off, int k,
                        const float* __restrict__ b_iouh, const float* __restrict__ b_fh) {
    int T = 2 * k;
    if (T >= 64) {
        float* h0 = (float*)sm; float* h1 = h0 + 256; float* hs = h1 + 256;
        for (int task = bid; task < T; task += NBLK) {
            int unit = (task >= k); int node = task - unit * k;
            const float *hsrc, *csrc; float *hdst, *cdst;
            if (mode == 0) { hsrc = g_mat[unit]; csrc = g_c[unit]; hdst = g_mat[unit]; cdst = g_c[unit]; }
            else { hsrc = g_hA[unit]; csrc = (lev == 1) ? g_c[1 - unit] : g_cA[unit];
                   hdst = g_hPre[unit]; cdst = g_cA[unit]; }
            int ch = (offp + 2 * node) * MEMD;
            float a = hsrc[ch + tid], b = hsrc[ch + MEMD + tid];
            h0[tid] = a; h1[tid] = b; hs[tid] = a + b;
            __syncthreads();
            float ai = 0, ao = 0, au = 0, af0 = 0, af1 = 0;
#pragma unroll 4
            for (int t = 0; t < MEMD; t++) {
                float4 w = g_Wpack[t * MEMD + tid];
                float hv = hs[t];
                ai  = fmaf(w.x, hv, ai);
                ao  = fmaf(w.y, hv, ao);
                au  = fmaf(w.z, hv, au);
                af0 = fmaf(w.w, h0[t], af0);
                af1 = fmaf(w.w, h1[t], af1);
            }
            float iv = sigm_acc(ai + b_iouh[tid]);
            float ov = sigm_acc(ao + b_iouh[256 + tid]);
            float uv = tanhf(au + b_iouh[512 + tid]);
            float f0 = sigm_acc(af0 + b_fh[tid]);
            float f1 = sigm_acc(af1 + b_fh[tid]);
            float c = iv * uv + f0 * csrc[ch + tid] + f1 * csrc[ch + MEMD + tid];
            float h = ov * tanhf(c);
            cdst[(off + node) * MEMD + tid] = c;
            hdst[(off + node) * MEMD + tid] = h;
            __syncthreads();
        }
    } else {
        // dim-split: blocks = T*8, each handles 32 output dims with 8-way e-split
        if (bid >= T * 8) return;
        float* h0 = (float*)sm; float* h1 = h0 + 256; float* red = h1 + 256; // red[8*32*5]
        int task = bid >> 3, grp = bid & 7;
        int unit = (task >= k); int node = task - unit * k;
        const float *hsrc, *csrc; float *hdst, *cdst;
        if (mode == 0) { hsrc = g_mat[unit]; csrc = g_c[unit]; hdst = g_mat[unit]; cdst = g_c[unit]; }
        else { hsrc = g_hA[unit]; csrc = (lev == 1) ? g_c[1 - unit] : g_cA[unit];
               hdst = g_hPre[unit]; cdst = g_cA[unit]; }
        int ch = (offp + 2 * node) * MEMD;
        h0[tid] = hsrc[ch + tid];
        h1[tid] = hsrc[ch + MEMD + tid];
        __syncthreads();
        int d = tid & 31, s = tid >> 5;
        int dim = grp * 32 + d;
        float ai = 0, ao = 0, au = 0, af0 = 0, af1 = 0;
        int e0 = s * 32;
#pragma unroll 8
        for (int ee = 0; ee < 32; ee++) {
            int e = e0 + ee;
            float4 w = g_Wpack[e * MEMD + dim];
            float hv = h0[e] + h1[e];
            ai  = fmaf(w.x, hv, ai);
            ao  = fmaf(w.y, hv, ao);
            au  = fmaf(w.z, hv, au);
            af0 = fmaf(w.w, h0[e], af0);
            af1 = fmaf(w.w, h1[e], af1);
        }
        float* rb = red + (s * 32 + d) * 5;
        rb[0] = ai; rb[1] = ao; rb[2] = au; rb[3] = af0; rb[4] = af1;
        __syncthreads();
        if (s == 0) {
            float A0 = 0, A1 = 0, A2 = 0, A3 = 0, A4 = 0;
#pragma unroll
            for (int ss = 0; ss < 8; ss++) {
                float* rr2 = red + (ss * 32 + d) * 5;
                A0 += rr2[0]; A1 += rr2[1]; A2 += rr2[2]; A3 += rr2[3]; A4 += rr2[4];
            }
            float iv = sigm_acc(A0 + b_iouh[dim]);
            float ov = sigm_acc(A1 + b_iouh[256 + dim]);
            float uv = tanhf(A2 + b_iouh[512 + dim]);
            float f0 = sigm_acc(A3 + b_fh[dim]);
            float f1 = sigm_acc(A4 + b_fh[dim]);
            float c = iv * uv + f0 * csrc[ch + dim] + f1 * csrc[ch + MEMD + dim];
            float h = ov * tanhf(c);
            cdst[(off + node) * MEMD + dim] = c;
            hdst[(off + node) * MEMD + dim] = h;
        }
    }
}

// proj (pb = mat@W2^T + b_attnh) + colsum(mat) per side
__device__ void st_proj(int bid, int tid, char* sm, const float* __restrict__ b_attnh) {
    if (bid < 256) {
        int side = bid >> 7; int mbase = (bid & 127) * 4;
        float* ms = (float*)sm;   // 4*256
#pragma unroll
        for (int r = 0; r < 4; r++) {
            int m = min(mbase + r, MTOT - 1);
            ms[r * 256 + tid] = g_mat[side][m * MEMD + tid];
        }
        __syncthreads();
        float ba = b_attnh[tid];
        float a0 = ba, a1 = ba, a2 = ba, a3 = ba;
#pragma unroll 4
        for (int e = 0; e < 256; e++) {
            float w = g_W2T[e * 256 + tid];
            a0 = fmaf(w, ms[e], a0);
            a1 = fmaf(w, ms[256 + e], a1);
            a2 = fmaf(w, ms[512 + e], a2);
            a3 = fmaf(w, ms[768 + e], a3);
        }
        if (mbase + 0 < MTOT) g_pb[side][(mbase + 0) * MEMD + tid] = a0;
        if (mbase + 1 < MTOT) g_pb[side][(mbase + 1) * MEMD + tid] = a1;
        if (mbase + 2 < MTOT) g_pb[side][(mbase + 2) * MEMD + tid] = a2;
        if (mbase + 3 < MTOT) g_pb[side][(mbase + 3) * MEMD + tid] = a3;
    } else if (bid < 264) {
        int s = bid - 256; int side = s >> 2; int qc = s & 3;
        int d = tid & 63; int rs = tid >> 6;
        int dim = qc * 64 + d;
        float a = 0.f;
        for (int m = rs; m < MTOT; m += 4) a += g_mat[side][m * MEMD + dim];
        float* red = (float*)sm;
        red[rs * 64 + d] = a;
        __syncthreads();
        if (rs == 0) g_colsum[side][dim] = red[d] + red[64 + d] + red[128 + d] + red[192 + d];
    }
}

// scores: raw attention scores for all rows of a level (or leaves)
__device__ void st_scores(int bid, int tid, char* sm, int leafst, int roff, int k,
                          const float* __restrict__ Wa) {
    int R = leafst ? 512 : 2 * k;
    int KS = leafst ? 1 : max(1, min(16, NBLK / R));
    int chunk = (MTOT + KS - 1) / KS;
    int total = R * KS;
    float* hrow = (float*)sm; float* hp = hrow + 256; float* wa = hp + 256;
    for (int job = bid; job < total; job += NBLK) {
        int r = job / KS, ck = job - r * KS;
        int p, n;
        if (leafst) { p = r >> 8; n = r & 255; } else { p = (r >= k); n = r - p * k; }
        int grow = roff + n;
        const float* hs_ = leafst ? g_mat[1 - p] : g_hPre[p];
        hrow[tid] = hs_[grow * MEMD + tid];
        wa[tid] = Wa[tid];
        __syncthreads();
        float acc = 0.f;
#pragma unroll 4
        for (int e = 0; e < 256; e++) acc = fmaf(g_W1T[e * 256 + tid], hrow[e], acc);
        hp[tid] = acc;
        __syncthreads();
        int warp = tid >> 5, lane = tid & 31;
        int m0 = ck * chunk, m1 = min(MTOT, m0 + chunk);
        const float* pbb = g_pb[p];
        for (int m = m0 + warp; m < m1; m += 8) {
            const float* pr = pbb + m * MEMD;
            float sc = 0.f;
#pragma unroll
            for (int dd = 0; dd < 8; dd++) {
                int d = dd * 32 + lane;
                sc = fmaf(tanh_fast(hp[d] + pr[d]), wa[d], sc);
            }
#pragma unroll
            for (int o = 16; o; o >>= 1) sc += __shfl_xor_sync(0xffffffffu, sc, o);
            if (lane == 0) g_scores[p][grow * MTOT + m] = sc;
        }
        __syncthreads();
    }
}

// softmax + combine: hA = colsum - (softmax @ mat) + h
__device__ void st_combine(int bid, int tid, char* sm, int leafst, int roff, int k) {
    int rpp = leafst ? 256 : k;
    int nbp = (rpp + 3) >> 2;
    int total = 2 * nbp;
    float* es   = (float*)sm;            // 4*512
    float* hsm  = es + 2048;             // 4*256
    float* red  = hsm + 1024;            // 256
    float* ssum = red + 256;             // 4
    float4* sp2 = (float4*)(ssum + 4);   // 4 strips * 4 rows * 64
    for (int job = bid; job < total; job += NBLK) {
        int p = job / nbp; int nbase = (job - p * nbp) * 4;
        const float* hs_ = leafst ? g_mat[1 - p] : g_hPre[p];
#pragma unroll
        for (int r = 0; r < 4; r++) {
            int n = min(nbase + r, rpp - 1);
            int grow = roff + n;
            const float* sr = g_scores[p] + grow * MTOT;
            float e0 = sr[tid];
            float e1 = (tid < 255) ? sr[256 + tid] : -1e30f;
            red[tid] = fmaxf(e0, e1);
            __syncthreads();
            for (int st = 128; st; st >>= 1) { if (tid < st) red[tid] = fmaxf(red[tid], red[tid + st]); __syncthreads(); }
            float mx = red[0];
            __syncthreads();
            float x0 = __expf(e0 - mx);
            float x1 = (tid < 255) ? __expf(e1 - mx) : 0.f;
            es[r * 512 + tid] = x0; es[r * 512 + 256 + tid] = x1;
            red[tid] = x0 + x1;
            __syncthreads();
            for (int st = 128; st; st >>= 1) { if (tid < st) red[tid] += red[tid + st]; __syncthreads(); }
            if (tid == 0) ssum[r] = red[0];
            hsm[r * 256 + tid] = hs_[grow * MEMD + tid];
            __syncthreads();
        }
        int q = tid & 63, strip = tid >> 6;
        const float4* mat4 = (const float4*)g_mat[p];
        float4 a2[4];
#pragma unroll
        for (int r = 0; r < 4; r++) a2[r] = make_float4(0, 0, 0, 0);
        for (int m = strip; m < MTOT; m += 4) {
            float4 mv = mat4[m * 64 + q];
#pragma unroll
            for (int r = 0; r < 4; r++) {
                float e = es[r * 512 + m];
                a2[r].x = fmaf(e, mv.x, a2[r].x);
                a2[r].y = fmaf(e, mv.y, a2[r].y);
                a2[r].z = fmaf(e, mv.z, a2[r].z);
                a2[r].w = fmaf(e, mv.w, a2[r].w);
            }
        }
#pragma unroll
        for (int r = 0; r < 4; r++) sp2[(strip * 4 + r) * 64 + q] = a2[r];
        __syncthreads();
        if (strip == 0) {
            const float* cs = g_colsum[p];
#pragma unroll
            for (int r = 0; r < 4; r++) {
                if (nbase + r < rpp) {
                    float4 t2 = sp2[r * 64 + q];
                    float4 tb = sp2[(4 + r) * 64 + q];
                    float4 tc = sp2[(8 + r) * 64 + q];
                    float4 td = sp2[(12 + r) * 64 + q];
                    t2.x += tb.x + tc.x + td.x;
                    t2.y += tb.y + tc.y + td.y;
                    t2.z += tb.z + tc.z + td.z;
                    t2.w += tb.w + tc.w + td.w;
                    float inv = 1.0f / ssum[r];
                    int grow = roff + nbase + r;
                    float* outp = g_hA[p] + grow * MEMD + 4 * q;
                    outp[0] = cs[4 * q + 0] - t2.x * inv + hsm[r * 256 + 4 * q + 0];
                    outp[1] = cs[4 * q + 1] - t2.y * inv + hsm[r * 256 + 4 * q + 1];
                    outp[2] = cs[4 * q + 2] - t2.z * inv + hsm[r * 256 + 4 * q + 2];
                    outp[3] = cs[4 * q + 3] - t2.w * inv + hsm[r * 256 + 4 * q + 3];
                }
            }
        }
        __syncthreads();
    }
}

__device__ void st_final(int tid, char* sm,
                         const float* __restrict__ W_wh, const float* __restrict__ b_wh,
                         const float* __restrict__ W_wp, const float* __restrict__ b_wp,
                         float* __restrict__ out) {
    float* v = (float*)sm; float* hid = v + 512;
    float lh = tanhf(g_mat[0][510 * MEMD + tid] + g_hA[1][510 * MEMD + tid]);
    float rh = tanhf(g_hA[0][510 * MEMD + tid] + g_mat[1][510 * MEMD + tid]);
    v[tid] = lh * rh;
    v[256 + tid] = fabsf(lh - rh);
    __syncthreads();
    if (tid < HIDD) {
        float a = b_wh[tid];
        for (int e = 0; e < 512; e++) a = fmaf(W_wh[tid * 512 + e], v[e], a);
        hid[tid] = sigm_acc(a);
    }
    __syncthreads();
    if (tid < 32) {
        float z[NCLS];
#pragma unroll
        for (int c = 0; c < NCLS; c++) {
            float a = 0.f;
            for (int e = tid; e < HIDD; e += 32) a = fmaf(W_wp[c * HIDD + e], hid[e], a);
#pragma unroll
            for (int o = 16; o; o >>= 1) a += __shfl_xor_sync(0xffffffffu, a, o);
            z[c] = a + b_wp[c];
        }
        if (tid == 0) {
            float mx = z[0];
#pragma unroll
            for (int c = 1; c < NCLS; c++) mx = fmaxf(mx, z[c]);
            float s = 0.f;
#pragma unroll
            for (int c = 0; c < NCLS; c++) s += expf(z[c] - mx);
            float ls = logf(s);
#pragma unroll
            for (int c = 0; c < NCLS; c++) out[c] = z[c] - mx - ls;
        }
    }
}

// ================= persistent mega kernel =================
__global__ void __launch_bounds__(256, 2)
mega_kernel(const int* l_idx, const int* r_idx, const float* emb,
            const float* W_ioux, const float* b_ioux,
            const float* W_iouh, const float* b_iouh,
            const float* W_fh, const float* b_fh,
            const float* Wa, const float* b_attnh,
            const float* W_attnh,
            const float* W_wh, const float* b_wh,
            const float* W_wp, const float* b_wp,
            float* out) {
    __shared__ __align__(16) char sm[30720];
    int bid = blockIdx.x, tid = threadIdx.x;
    int b = 0;
    const int off[9] = {0, 256, 384, 448, 480, 496, 504, 508, 510};

    st_prep(bid, tid, W_ioux, W_iouh, W_fh, W_attnh);            gbar(b++);
    st_leafgemm(bid, tid, sm, l_idx, r_idx, emb, b_ioux, b_iouh); gbar(b++);
    st_leafgate(bid, tid);                                        gbar(b++);

    for (int lev = 1; lev <= 8; lev++) {
        st_tree(bid, tid, sm, 0, lev, off[lev - 1], off[lev], LN >> lev, b_iouh, b_fh);
        gbar(b++);
    }

    st_proj(bid, tid, sm, b_attnh);            gbar(b++);
    st_scores(bid, tid, sm, 1, 0, 0, Wa);      gbar(b++);
    st_combine(bid, tid, sm, 1, 0, 0);         gbar(b++);

    for (int lev = 1; lev <= 8; lev++) {
        int k = LN >> lev;
        st_tree(bid, tid, sm, 1, lev, off[lev - 1], off[lev], k, b_iouh, b_fh); gbar(b++);
        st_scores(bid, tid, sm, 0, off[lev], k, Wa);                            gbar(b++);
        st_combine(bid, tid, sm, 0, off[lev], k);                               gbar(b++);
    }

    if (bid == 0) st_final(tid, sm, W_wh, b_wh, W_wp, b_wp, out);
}

// ================= host =================
extern "C" void kernel_launch(void* const* d_in, const int* in_sizes, int n_in,
                              void* d_out, int out_size) {
    const int*   l_idx   = (const int*)d_in[0];
    const int*   r_idx   = (const int*)d_in[1];
    const float* emb     = (const float*)d_in[2];
    const float* W_ioux  = (const float*)d_in[3];
    const float* b_ioux  = (const float*)d_in[4];
    const float* W_iouh  = (const float*)d_in[5];
    const float* b_iouh  = (const float*)d_in[6];
    // d_in[7]=W_fx, d_in[8]=b_fx unused by reference
    const float* W_fh    = (const float*)d_in[9];
    const float* b_fh    = (const float*)d_in[10];
    const float* Wa      = (const float*)d_in[11];
    const float* W_attnh = (const float*)d_in[12];
    const float* b_attnh = (const float*)d_in[13];
    const float* W_wh    = (const float*)d_in[14];
    const float* b_wh    = (const float*)d_in[15];
    const float* W_wp    = (const float*)d_in[16];
    const float* b_wp    = (const float*)d_in[17];
    float* out = (float*)d_out;

    reset_kernel<<<1, 64>>>();
    mega_kernel<<<NBLK, 256>>>(l_idx, r_idx, emb,
                               W_ioux, b_ioux, W_iouh, b_iouh, W_fh, b_fh,
                               Wa, b_attnh, W_attnh,
                               W_wh, b_wh, W_wp, b_wp, out);
}

// round 5
// speedup vs baseline: 1.1172x; 1.1172x over previous
#include <cuda_runtime.h>
#include <math.h>

#define NBLK 296
#define MTOT 511

// ---------------- device scratch ----------------
__device__ float  g_WxT[300 * 768];
__device__ float4 g_Wpack[65536];          // {Wh_i,Wh_o,Wh_u,Wf}[e][j]
__device__ float  g_W1T[65536];            // W_attnh[:, :256]^T [e][d]
__device__ float  g_W2T[65536];            // W_attnh[:, 256:]^T [e][d]
__device__ float  g_iou[512 * 768];
__device__ float  g_mat[2][MTOT * 256];
__device__ float  g_c[2][MTOT * 256];
__device__ float  g_hA[2][MTOT * 256];
__device__ float  g_cA[2][MTOT * 256];
__device__ float  g_hPre[2][MTOT * 256];
__device__ float  g_pbT[2][256 * 512];     // transposed proj+bias: [d][m]
__device__ float  g_colsum[2][256];
__device__ float  g_hp[2][16 * 256];       // deep-level hp rows
__device__ float  g_scD[2][16 * 512];      // deep-level raw scores
__device__ float  g_treePart[1024 * 1280]; // (task*ES+es) -> 5x256 partials
__device__ int    g_bar[64];

__constant__ int c_off[9] = {0, 256, 384, 448, 480, 496, 504, 508, 510};
__constant__ int c_RT[9]  = {0, 8, 8, 8, 8, 8, 8, 4, 2};
__constant__ int c_ES[9]  = {0, 4, 8, 16, 32, 32, 32, 32, 32};
__constant__ int c_KS[9]  = {0, 0, 0, 0, 8, 16, 16, 16, 16};

__device__ __forceinline__ float sigm(float x) { return 1.0f / (1.0f + expf(-x)); }
__device__ __forceinline__ float tfast(float x) {
    float y; asm("tanh.approx.f32 %0,%1;" : "=f"(y) : "f"(x)); return y;
}

// ---------------- global software barrier ----------------
__device__ __forceinline__ void gbar(int id) {
    __syncthreads();
    if (threadIdx.x == 0) {
        __threadfence();
        atomicAdd(&g_bar[id], 1);
        while (((volatile int*)g_bar)[id] < NBLK) __nanosleep(64);
        __threadfence();
    }
    __syncthreads();
}

__global__ void reset_kernel() {
    if (threadIdx.x < 64) g_bar[threadIdx.x] = 0;
}

// ---------------- block reductions (256 thr) ----------------
__device__ __forceinline__ float blkmax(float v, float* red, int tid) {
    for (int o = 16; o; o >>= 1) v = fmaxf(v, __shfl_xor_sync(~0u, v, o));
    if ((tid & 31) == 0) red[tid >> 5] = v;
    __syncthreads();
    if (tid == 0) { float m = red[0]; for (int i = 1; i < 8; i++) m = fmaxf(m, red[i]); red[8] = m; }
    __syncthreads();
    float r = red[8]; __syncthreads(); return r;
}
__device__ __forceinline__ float blksum(float v, float* red, int tid) {
    for (int o = 16; o; o >>= 1) v += __shfl_xor_sync(~0u, v, o);
    if ((tid & 31) == 0) red[tid >> 5] = v;
    __syncthreads();
    if (tid == 0) { float s = 0; for (int i = 0; i < 8; i++) s += red[i]; red[8] = s; }
    __syncthreads();
    float r = red[8]; __syncthreads(); return r;
}

// ================= stages =================

__device__ void st_prep(int bid, int tid,
                        const float* __restrict__ W_ioux, const float* __restrict__ W_iouh,
                        const float* __restrict__ W_fh,   const float* __restrict__ W_attnh) {
    const int N1 = 300 * 768, N2 = 65536, N3 = 65536, N4 = 65536;
    for (int i = bid * 256 + tid; i < N1 + N2 + N3 + N4; i += NBLK * 256) {
        if (i < N1) {
            int t = i / 768, j = i - t * 768;
            g_WxT[i] = W_ioux[j * 300 + t];
        } else if (i < N1 + N2) {
            int e = i - N1; int t = e >> 8, j = e & 255;
            g_Wpack[e] = make_float4(W_iouh[j * 256 + t], W_iouh[(256 + j) * 256 + t],
                                     W_iouh[(512 + j) * 256 + t], W_fh[j * 256 + t]);
        } else if (i < N1 + N2 + N3) {
            int e = i - N1 - N2; int ee = e >> 8, d = e & 255;
            g_W1T[e] = W_attnh[d * 512 + ee];
        } else {
            int e = i - N1 - N2 - N3; int ee = e >> 8, d = e & 255;
            g_W2T[e] = W_attnh[d * 512 + 256 + ee];
        }
    }
}

__device__ void st_leafgemm(int bid, int tid, float* smf,
                            const int* __restrict__ l_idx, const int* __restrict__ r_idx,
                            const float* __restrict__ emb,
                            const float* __restrict__ b_ioux, const float* __restrict__ b_iouh) {
    if (bid >= 192) return;
    float* xs = smf;                  // 8*300
    int* sidx = (int*)(smf + 2400);
    int rowgrp = bid & 63, part = bid >> 6;
    if (tid < 8) {
        int grow = rowgrp * 8 + tid;
        sidx[tid] = (grow >= 256) ? r_idx[grow - 256] : l_idx[grow];
    }
    __syncthreads();
    for (int e = tid; e < 8 * 300; e += 256) {
        int rr = e / 300, t = e - rr * 300;
        xs[e] = emb[(long)sidx[rr] * 300 + t];
    }
    __syncthreads();
    int col = part * 256 + tid;
    float bias = b_ioux[col] + b_iouh[col];
    float acc[8];
#pragma unroll
    for (int r = 0; r < 8; r++) acc[r] = bias;
#pragma unroll 4
    for (int t = 0; t < 300; t++) {
        float w = g_WxT[t * 768 + col];
#pragma unroll
        for (int r = 0; r < 8; r++) acc[r] = fmaf(w, xs[r * 300 + t], acc[r]);
    }
#pragma unroll
    for (int r = 0; r < 8; r++) g_iou[(rowgrp * 8 + r) * 768 + col] = acc[r];
}

__device__ void st_leafgate(int bid, int tid) {
    for (int row = bid; row < 512; row += NBLK) {
        int side = row >> 8, leaf = row & 255;
        const float* base = &g_iou[row * 768];
        float iv = sigm(base[tid]);
        float ov = sigm(base[256 + tid]);
        float uv = tanhf(base[512 + tid]);
        float c = iv * uv;
        float h = ov * tanhf(c);
        g_c[side][leaf * 256 + tid] = c;
        g_mat[side][leaf * 256 + tid] = h;
    }
}

// split-K tree GEMM partials
template <int RT>
__device__ void st_accum(int bid, int tid, float* smf, int mode, int lev) {
    int k = 256 >> lev, T = 2 * k, ES = c_ES[lev];
    int tg_cnt = T / RT;
    if (bid >= tg_cnt * ES) return;
    int tg = bid / ES, es = bid - tg * ES;
    int eNa = 256 / ES, e0 = es * eNa;
    int offp = c_off[lev - 1];
    int cnt = RT * 2 * eNa;
    for (int t = tid; t < cnt; t += 256) {
        int r = t / (2 * eNa); int rem = t - r * 2 * eNa;
        int cc = rem / eNa; int e = rem - cc * eNa;
        int task = tg * RT + r; int p = task >= k; int node = task - p * k;
        const float* hsrc = mode ? g_hA[p] : g_mat[p];
        smf[t] = hsrc[(offp + 2 * node + cc) * 256 + e0 + e];
    }
    __syncthreads();
    float a0[RT], a1[RT], a2[RT], a3[RT], a4[RT];
#pragma unroll
    for (int r = 0; r < RT; r++) { a0[r] = a1[r] = a2[r] = a3[r] = a4[r] = 0.f; }
#pragma unroll 4
    for (int ee = 0; ee < eNa; ee++) {
        float4 w = g_Wpack[(e0 + ee) * 256 + tid];
#pragma unroll
        for (int r = 0; r < RT; r++) {
            float h0 = smf[r * 2 * eNa + ee], h1 = smf[r * 2 * eNa + eNa + ee];
            float hv = h0 + h1;
            a0[r] = fmaf(w.x, hv, a0[r]); a1[r] = fmaf(w.y, hv, a1[r]);
            a2[r] = fmaf(w.z, hv, a2[r]);
            a3[r] = fmaf(w.w, h0, a3[r]); a4[r] = fmaf(w.w, h1, a4[r]);
        }
    }
#pragma unroll
    for (int r = 0; r < RT; r++) {
        float* b = &g_treePart[((tg * RT + r) * ES + es) * 1280];
        b[tid] = a0[r]; b[256 + tid] = a1[r]; b[512 + tid] = a2[r];
        b[768 + tid] = a3[r]; b[1024 + tid] = a4[r];
    }
}

__device__ void accum_d(int bid, int tid, float* smf, int mode, int lev) {
    int rt = c_RT[lev];
    if (rt == 8) st_accum<8>(bid, tid, smf, mode, lev);
    else if (rt == 4) st_accum<4>(bid, tid, smf, mode, lev);
    else st_accum<2>(bid, tid, smf, mode, lev);
}

// gate: reduce ES partials + LSTM cell; mode1 = attended (hPre/cA); lev>=4 mode1 also computes hp
__device__ void st_gate(int bid, int tid, float* smf, int mode, int lev,
                        const float* __restrict__ bi, const float* __restrict__ bf) {
    int k = 256 >> lev, T = 2 * k, ES = c_ES[lev];
    if (bid >= T) return;
    int p = bid >= k; int node = bid - p * k;
    int offp = c_off[lev - 1], offc = c_off[lev];
    float s0 = 0, s1 = 0, s2 = 0, s3 = 0, s4 = 0;
    for (int s = 0; s < ES; s++) {
        const float* b = &g_treePart[(bid * ES + s) * 1280];
        s0 += __ldcg(b + tid);       s1 += __ldcg(b + 256 + tid);
        s2 += __ldcg(b + 512 + tid); s3 += __ldcg(b + 768 + tid);
        s4 += __ldcg(b + 1024 + tid);
    }
    float iv = sigm(s0 + bi[tid]), ov = sigm(s1 + bi[256 + tid]);
    float uv = tanhf(s2 + bi[512 + tid]);
    float f0 = sigm(s3 + bf[tid]), f1 = sigm(s4 + bf[tid]);
    const float* csrc = mode ? ((lev == 1) ? &g_c[1 - p][(2 * node) * 256]
                                           : &g_cA[p][(offp + 2 * node) * 256])
                             : &g_c[p][(offp + 2 * node) * 256];
    float c = iv * uv + f0 * csrc[tid] + f1 * csrc[256 + tid];
    float h = ov * tanhf(c);
    if (mode) { g_cA[p][(offc + node) * 256 + tid] = c; g_hPre[p][(offc + node) * 256 + tid] = h; }
    else      { g_c[p][(offc + node) * 256 + tid] = c;  g_mat[p][(offc + node) * 256 + tid] = h; }
    if (mode && lev >= 4) {  // fused hp = W1 @ h
        float* hsm = smf; float* hpP = smf + 256;
        hsm[tid] = h;
        __syncthreads();
        int w = tid >> 5, lane = tid & 31;
        float a[8] = {0, 0, 0, 0, 0, 0, 0, 0};
        for (int ei = 0; ei < 32; ei++) {
            int e = w * 32 + ei; float hv = hsm[e];
#pragma unroll
            for (int c2 = 0; c2 < 8; c2++) a[c2] = fmaf(g_W1T[e * 256 + c2 * 32 + lane], hv, a[c2]);
        }
#pragma unroll
        for (int c2 = 0; c2 < 8; c2++) hpP[w * 256 + c2 * 32 + lane] = a[c2];
        __syncthreads();
        float s = 0;
#pragma unroll
        for (int w2 = 0; w2 < 8; w2++) s += hpP[w2 * 256 + tid];
        g_hp[p][node * 256 + tid] = s;
    }
}

// proj -> pbT (transposed) + colsum + pad
__device__ void st_projx(int bid, int tid, float* smf, const float* __restrict__ ba) {
    if (bid < 256) {
        int side = bid >> 7, mb = (bid & 127) * 4;
        float* ms = smf;
#pragma unroll
        for (int r = 0; r < 4; r++) {
            int m = min(mb + r, 510);
            ms[r * 256 + tid] = g_mat[side][m * 256 + tid];
        }
        __syncthreads();
        float b0 = ba[tid]; float a0 = b0, a1 = b0, a2 = b0, a3 = b0;
#pragma unroll 4
        for (int e = 0; e < 256; e++) {
            float w = g_W2T[e * 256 + tid];
            a0 = fmaf(w, ms[e], a0);       a1 = fmaf(w, ms[256 + e], a1);
            a2 = fmaf(w, ms[512 + e], a2); a3 = fmaf(w, ms[768 + e], a3);
        }
        float* pt = g_pbT[side];
        pt[tid * 512 + mb] = a0;
        if (mb + 1 < 511) pt[tid * 512 + mb + 1] = a1;
        if (mb + 2 < 511) pt[tid * 512 + mb + 2] = a2;
        if (mb + 3 < 511) pt[tid * 512 + mb + 3] = a3;
    } else if (bid < 264) {
        int s = bid - 256, side = s >> 2, qc = s & 3;
        if (qc == 0) g_pbT[side][tid * 512 + 511] = 0.f;  // pad key 511
        int d = tid & 63, rs = tid >> 6, dim = qc * 64 + d;
        float a = 0;
        for (int m = rs; m < 511; m += 4) a += g_mat[side][m * 256 + dim];
        float* red = smf;
        red[rs * 64 + d] = a;
        __syncthreads();
        if (rs == 0) g_colsum[side][dim] = red[d] + red[64 + d] + red[128 + d] + red[192 + d];
    }
}

// fused attend: hp + scores + softmax + combine, R rows/block, all 511 keys
template <int R>
__device__ void st_attend(int bid, int tid, float* smf, int lev, const float* __restrict__ Wa) {
    int rows_pp = (lev == 0) ? 256 : (256 >> lev);
    int rg = rows_pp / R;
    if (bid >= 2 * rg) return;
    int p = bid >= rg; int nb = (bid - p * rg) * R;
    int roff = c_off[lev];   // 0 for leaves
    float* hsm = smf;                     // R*256
    float* wa  = smf + R * 256;           // 256
    float* hpP = wa + 256;                // 8*R*256 (first R*256 reused as final hp)
    float* es  = hpP + 8 * R * 256;       // R*512
    float* red = es + R * 512;            // 9
    const float* hsrc = lev ? g_hPre[p] : g_mat[1 - p];
#pragma unroll
    for (int r = 0; r < R; r++) hsm[r * 256 + tid] = hsrc[(roff + nb + r) * 256 + tid];
    wa[tid] = Wa[tid];
    __syncthreads();
    int w = tid >> 5, lane = tid & 31;
    {   // hp partials: warp w covers e in [32w, 32w+32)
        float acc[R][8];
#pragma unroll
        for (int r = 0; r < R; r++)
#pragma unroll
            for (int c = 0; c < 8; c++) acc[r][c] = 0.f;
        for (int ei = 0; ei < 32; ei++) {
            int e = w * 32 + ei;
#pragma unroll
            for (int c = 0; c < 8; c++) {
                float w1 = g_W1T[e * 256 + c * 32 + lane];
#pragma unroll
                for (int r = 0; r < R; r++) acc[r][c] = fmaf(w1, hsm[r * 256 + e], acc[r][c]);
            }
        }
#pragma unroll
        for (int r = 0; r < R; r++)
#pragma unroll
            for (int c = 0; c < 8; c++) hpP[w * R * 256 + r * 256 + c * 32 + lane] = acc[r][c];
    }
    __syncthreads();
    float hpr[R];
#pragma unroll
    for (int r = 0; r < R; r++) {
        float s = 0;
#pragma unroll
        for (int w2 = 0; w2 < 8; w2++) s += hpP[w2 * R * 256 + r * 256 + tid];
        hpr[r] = s;
    }
    __syncthreads();
#pragma unroll
    for (int r = 0; r < R; r++) hpP[r * 256 + tid] = hpr[r];
    __syncthreads();
    // scores: warp w owns key strips w (0..255) and w+8 (256..511); lane = key
    float sa[R][2];
#pragma unroll
    for (int r = 0; r < R; r++) { sa[r][0] = 0.f; sa[r][1] = 0.f; }
    const float* pbb = g_pbT[p];
#pragma unroll 4
    for (int d = 0; d < 256; d++) {
        float pb0 = pbb[d * 512 + w * 32 + lane];
        float pb1 = pbb[d * 512 + 256 + w * 32 + lane];
        float wv = wa[d];
#pragma unroll
        for (int r = 0; r < R; r++) {
            float hv = hpP[r * 256 + d];
            sa[r][0] = fmaf(wv, tfast(hv + pb0), sa[r][0]);
            sa[r][1] = fmaf(wv, tfast(hv + pb1), sa[r][1]);
        }
    }
#pragma unroll
    for (int r = 0; r < R; r++) {
        es[r * 512 + w * 32 + lane] = sa[r][0];
        es[r * 512 + 256 + w * 32 + lane] = sa[r][1];
    }
    __syncthreads();
    float inv[R];
#pragma unroll
    for (int r = 0; r < R; r++) {
        float e0 = es[r * 512 + tid];
        float e1 = (tid < 255) ? es[r * 512 + 256 + tid] : -1e30f;
        float mx = blkmax(fmaxf(e0, e1), red, tid);
        float x0 = __expf(e0 - mx);
        float x1 = (tid < 255) ? __expf(e1 - mx) : 0.f;
        es[r * 512 + tid] = x0; es[r * 512 + 256 + tid] = x1;
        inv[r] = 1.0f / blksum(x0 + x1, red, tid);
    }
    __syncthreads();
    float acc2[R];
#pragma unroll
    for (int r = 0; r < R; r++) acc2[r] = 0.f;
    const float* mb = g_mat[p];
#pragma unroll 4
    for (int m = 0; m < 511; m++) {
        float mv = mb[m * 256 + tid];
#pragma unroll
        for (int r = 0; r < R; r++) acc2[r] = fmaf(es[r * 512 + m], mv, acc2[r]);
    }
    const float* cs = g_colsum[p];
#pragma unroll
    for (int r = 0; r < R; r++)
        g_hA[p][(roff + nb + r) * 256 + tid] = cs[tid] - acc2[r] * inv[r] + hsm[r * 256 + tid];
}

// deep-level scores: key-split blocks, warps d-split + smem reduce
__device__ void st_scoresD(int bid, int tid, float* smf, int lev, const float* __restrict__ Wa) {
    int k = 256 >> lev, KS = c_KS[lev];
    int per = k * KS;
    if (bid >= 2 * per) return;
    int p = bid >= per; int rem = bid - p * per;
    int n = rem / KS, ck = rem - n * KS;
    int chunk = 512 / KS;
    float* hr = smf; float* wa = smf + 256; float* part = smf + 512;
    hr[tid] = __ldcg(&g_hp[p][n * 256 + tid]);
    wa[tid] = Wa[tid];
    __syncthreads();
    int w = tid >> 5, lane = tid & 31;
    int ns = chunk >> 5, DW = 8 / ns, dch = 256 / DW;
    int sg = w % ns, dg = w / ns;
    int m = ck * chunk + sg * 32 + lane;
    float a = 0.f;
    const float* pbb = g_pbT[p];
#pragma unroll 4
    for (int dd = 0; dd < dch; dd++) {
        int d = dg * dch + dd;
        a = fmaf(wa[d], tfast(hr[d] + pbb[d * 512 + m]), a);
    }
    part[dg * chunk + sg * 32 + lane] = a;
    __syncthreads();
    if (tid < chunk) {
        float s = 0;
        for (int g = 0; g < DW; g++) s += part[g * chunk + tid];
        int mm = ck * chunk + tid;
        if (mm < 511) g_scD[p][n * 512 + mm] = s;
    }
}

// deep-level softmax + combine
__device__ void st_combineD(int bid, int tid, float* smf, int lev) {
    int k = 256 >> lev;
    if (bid >= 2 * k) return;
    int p = bid >= k; int n = bid - p * k;
    int grow = c_off[lev] + n;
    float* es = smf; float* hr = smf + 512; float* red = smf + 768;
    float4* sp = (float4*)(smf + 832);
    float e0 = __ldcg(&g_scD[p][n * 512 + tid]);
    float e1 = (tid < 255) ? __ldcg(&g_scD[p][n * 512 + 256 + tid]) : -1e30f;
    hr[tid] = g_hPre[p][grow * 256 + tid];
    float mx = blkmax(fmaxf(e0, e1), red, tid);
    float x0 = __expf(e0 - mx), x1 = (tid < 255) ? __expf(e1 - mx) : 0.f;
    es[tid] = x0; es[256 + tid] = x1;
    float inv = 1.0f / blksum(x0 + x1, red, tid);
    __syncthreads();
    int q = tid & 63, st = tid >> 6;
    const float4* m4 = (const float4*)g_mat[p];
    float4 a = make_float4(0, 0, 0, 0);
    for (int m = st; m < 511; m += 4) {
        float4 mv = m4[m * 64 + q]; float e = es[m];
        a.x = fmaf(e, mv.x, a.x); a.y = fmaf(e, mv.y, a.y);
        a.z = fmaf(e, mv.z, a.z); a.w = fmaf(e, mv.w, a.w);
    }
    sp[st * 64 + q] = a;
    __syncthreads();
    if (st == 0) {
        float4 t = sp[q], b1 = sp[64 + q], b2 = sp[128 + q], b3 = sp[192 + q];
        t.x += b1.x + b2.x + b3.x; t.y += b1.y + b2.y + b3.y;
        t.z += b1.z + b2.z + b3.z; t.w += b1.w + b2.w + b3.w;
        const float* cs = g_colsum[p];
        float* o = &g_hA[p][grow * 256 + 4 * q];
        o[0] = cs[4 * q + 0] - t.x * inv + hr[4 * q + 0];
        o[1] = cs[4 * q + 1] - t.y * inv + hr[4 * q + 1];
        o[2] = cs[4 * q + 2] - t.z * inv + hr[4 * q + 2];
        o[3] = cs[4 * q + 3] - t.w * inv + hr[4 * q + 3];
    }
}

__device__ void st_final(int tid, float* smf,
                         const float* __restrict__ W_wh, const float* __restrict__ b_wh,
                         const float* __restrict__ W_wp, const float* __restrict__ b_wp,
                         float* __restrict__ out) {
    float* v = smf; float* hid = smf + 512;
    float lh = tanhf(g_mat[0][510 * 256 + tid] + g_hA[1][510 * 256 + tid]);
    float rh = tanhf(g_hA[0][510 * 256 + tid] + g_mat[1][510 * 256 + tid]);
    v[tid] = lh * rh;
    v[256 + tid] = fabsf(lh - rh);
    __syncthreads();
    if (tid < 128) {
        float a = b_wh[tid];
        for (int e = 0; e < 512; e++) a = fmaf(W_wh[tid * 512 + e], v[e], a);
        hid[tid] = sigm(a);
    }
    __syncthreads();
    if (tid < 32) {
        float z[5];
#pragma unroll
        for (int c = 0; c < 5; c++) {
            float a = 0.f;
            for (int e = tid; e < 128; e += 32) a = fmaf(W_wp[c * 128 + e], hid[e], a);
#pragma unroll
            for (int o = 16; o; o >>= 1) a += __shfl_xor_sync(~0u, a, o);
            z[c] = a + b_wp[c];
        }
        if (tid == 0) {
            float mx = z[0];
#pragma unroll
            for (int c = 1; c < 5; c++) mx = fmaxf(mx, z[c]);
            float s = 0.f;
#pragma unroll
            for (int c = 0; c < 5; c++) s += expf(z[c] - mx);
            float ls = logf(s);
#pragma unroll
            for (int c = 0; c < 5; c++) out[c] = z[c] - mx - ls;
        }
    }
}

// ================= persistent mega kernel =================
__global__ void __launch_bounds__(256, 2)
mega_kernel(const int* l_idx, const int* r_idx, const float* emb,
            const float* W_ioux, const float* b_ioux,
            const float* W_iouh, const float* b_iouh,
            const float* W_fh, const float* b_fh,
            const float* Wa, const float* b_attnh,
            const float* W_wh, const float* b_wh,
            const float* W_wp, const float* b_wp,
            const float* W_attnh, float* out) {
    __shared__ __align__(16) float smf[11600];
    int bid = blockIdx.x, tid = threadIdx.x;
    int b = 0;

    st_prep(bid, tid, W_ioux, W_iouh, W_fh, W_attnh);               gbar(b++);
    st_leafgemm(bid, tid, smf, l_idx, r_idx, emb, b_ioux, b_iouh);  gbar(b++);
    st_leafgate(bid, tid);                                          gbar(b++);

    for (int lev = 1; lev <= 8; lev++) {
        accum_d(bid, tid, smf, 0, lev);                 gbar(b++);
        st_gate(bid, tid, smf, 0, lev, b_iouh, b_fh);   gbar(b++);
    }

    st_projx(bid, tid, smf, b_attnh);                   gbar(b++);
    st_attend<4>(bid, tid, smf, 0, Wa);                 gbar(b++);

    for (int lev = 1; lev <= 3; lev++) {
        accum_d(bid, tid, smf, 1, lev);                 gbar(b++);
        st_gate(bid, tid, smf, 1, lev, b_iouh, b_fh);   gbar(b++);
        if (lev == 1) st_attend<2>(bid, tid, smf, 1, Wa);
        else          st_attend<1>(bid, tid, smf, lev, Wa);
        gbar(b++);
    }

    for (int lev = 4; lev <= 8; lev++) {
        accum_d(bid, tid, smf, 1, lev);                 gbar(b++);
        st_gate(bid, tid, smf, 1, lev, b_iouh, b_fh);   gbar(b++);
        st_scoresD(bid, tid, smf, lev, Wa);             gbar(b++);
        st_combineD(bid, tid, smf, lev);                gbar(b++);
    }

    if (bid == 0) st_final(tid, smf, W_wh, b_wh, W_wp, b_wp, out);
}

// ================= host =================
extern "C" void kernel_launch(void* const* d_in, const int* in_sizes, int n_in,
                              void* d_out, int out_size) {
    const int*   l_idx   = (const int*)d_in[0];
    const int*   r_idx   = (const int*)d_in[1];
    const float* emb     = (const float*)d_in[2];
    const float* W_ioux  = (const float*)d_in[3];
    const float* b_ioux  = (const float*)d_in[4];
    const float* W_iouh  = (const float*)d_in[5];
    const float* b_iouh  = (const float*)d_in[6];
    // d_in[7]=W_fx, d_in[8]=b_fx unused by reference
    const float* W_fh    = (const float*)d_in[9];
    const float* b_fh    = (const float*)d_in[10];
    const float* Wa      = (const float*)d_in[11];
    const float* W_attnh = (const float*)d_in[12];
    const float* b_attnh = (const float*)d_in[13];
    const float* W_wh    = (const float*)d_in[14];
    const float* b_wh    = (const float*)d_in[15];
    const float* W_wp    = (const float*)d_in[16];
    const float* b_wp    = (const float*)d_in[17];
    float* out = (float*)d_out;

    reset_kernel<<<1, 64>>>();
    mega_kernel<<<NBLK, 256>>>(l_idx, r_idx, emb,
                               W_ioux, b_ioux, W_iouh, b_iouh, W_fh, b_fh,
                               Wa, b_attnh, W_wh, b_wh, W_wp, b_wp,
                               W_attnh, out);
}

// round 6
// speedup vs baseline: 1.2082x; 1.0814x over previous
#include <cuda_runtime.h>
#include <math.h>

#define NBLK 296
#define GBLK 148
#define MTOT 511

// ---------------- device scratch ----------------
__device__ float  g_WxT[300 * 768];
__device__ float4 g_Wpack[65536];            // {Wh_i,Wh_o,Wh_u,Wf}[e][j]
__device__ float  g_W1T[65536];              // W_attnh[:, :256]^T [e][d]
__device__ float  g_W2T[65536];              // W_attnh[:, 256:]^T [e][d]
__device__ float  g_iou[512 * 768];
__device__ float  g_mat[2][MTOT * 256];
__device__ float  g_c[2][MTOT * 256];
__device__ float  g_hA[2][MTOT * 256];
__device__ float  g_cA[2][MTOT * 256];
__device__ float  g_hPre[2][MTOT * 256];
__device__ float  g_pbT[2][256 * 512];       // transposed proj+bias: [d][m]
__device__ float  g_colsum[2][256];
__device__ float  g_hp[2][16 * 256];
__device__ float  g_treePart[2][1024 * 1280];
__device__ int    g_barG[8];
__device__ int    g_barL[2][48];

__constant__ int c_off[9] = {0, 256, 384, 448, 480, 496, 504, 508, 510};
__constant__ int c_RT[9]  = {0, 8, 8, 8, 8, 8, 4, 2, 1};
__constant__ int c_ES[9]  = {0, 8, 16, 32, 32, 16, 16, 16, 16};

__device__ __forceinline__ float sigm(float x) { return 1.0f / (1.0f + expf(-x)); }
__device__ __forceinline__ float tfast(float x) {
    float y; asm("tanh.approx.f32 %0,%1;" : "=f"(y) : "f"(x)); return y;
}

// ---------------- barriers ----------------
__device__ __forceinline__ void gbarG(int id) {
    __syncthreads();
    if (threadIdx.x == 0) {
        __threadfence();
        atomicAdd(&g_barG[id], 1);
        while (((volatile int*)g_barG)[id] < NBLK) __nanosleep(64);
        __threadfence();
    }
    __syncthreads();
}
__device__ __forceinline__ void gbarL(int g, int id) {
    __syncthreads();
    if (threadIdx.x == 0) {
        __threadfence();
        atomicAdd(&g_barL[g][id], 1);
        while (((volatile int*)g_barL[g])[id] < GBLK) __nanosleep(64);
        __threadfence();
    }
    __syncthreads();
}

__global__ void reset_kernel() {
    if (threadIdx.x < 8) g_barG[threadIdx.x] = 0;
    if (threadIdx.x < 96) g_barL[threadIdx.x / 48][threadIdx.x % 48] = 0;
}

// ---------------- block reductions ----------------
__device__ __forceinline__ float blkmax(float v, float* red, int tid) {
    for (int o = 16; o; o >>= 1) v = fmaxf(v, __shfl_xor_sync(~0u, v, o));
    if ((tid & 31) == 0) red[tid >> 5] = v;
    __syncthreads();
    if (tid == 0) { float m = red[0]; for (int i = 1; i < 8; i++) m = fmaxf(m, red[i]); red[8] = m; }
    __syncthreads();
    float r = red[8]; __syncthreads(); return r;
}
__device__ __forceinline__ float blksum(float v, float* red, int tid) {
    for (int o = 16; o; o >>= 1) v += __shfl_xor_sync(~0u, v, o);
    if ((tid & 31) == 0) red[tid >> 5] = v;
    __syncthreads();
    if (tid == 0) { float s = 0; for (int i = 0; i < 8; i++) s += red[i]; red[8] = s; }
    __syncthreads();
    float r = red[8]; __syncthreads(); return r;
}

// ================= shared stages (all 296 blocks) =================

__device__ void st_prep(int bid, int tid,
                        const float* __restrict__ W_ioux, const float* __restrict__ W_iouh,
                        const float* __restrict__ W_fh,   const float* __restrict__ W_attnh) {
    const int N1 = 300 * 768, N2 = 65536, N3 = 65536, N4 = 65536;
    for (int i = bid * 256 + tid; i < N1 + N2 + N3 + N4; i += NBLK * 256) {
        if (i < N1) {
            int t = i / 768, j = i - t * 768;
            g_WxT[i] = W_ioux[j * 300 + t];
        } else if (i < N1 + N2) {
            int e = i - N1; int t = e >> 8, j = e & 255;
            g_Wpack[e] = make_float4(W_iouh[j * 256 + t], W_iouh[(256 + j) * 256 + t],
                                     W_iouh[(512 + j) * 256 + t], W_fh[j * 256 + t]);
        } else if (i < N1 + N2 + N3) {
            int e = i - N1 - N2; int ee = e >> 8, d = e & 255;
            g_W1T[e] = W_attnh[d * 512 + ee];
        } else {
            int e = i - N1 - N2 - N3; int ee = e >> 8, d = e & 255;
            g_W2T[e] = W_attnh[d * 512 + 256 + ee];
        }
    }
}

__device__ void st_leafgemm(int bid, int tid, float* smf,
                            const int* __restrict__ l_idx, const int* __restrict__ r_idx,
                            const float* __restrict__ emb,
                            const float* __restrict__ b_ioux, const float* __restrict__ b_iouh) {
    if (bid >= 192) return;
    float* xs = smf;
    int* sidx = (int*)(smf + 2400);
    int rowgrp = bid & 63, part = bid >> 6;
    if (tid < 8) {
        int grow = rowgrp * 8 + tid;
        sidx[tid] = (grow >= 256) ? r_idx[grow - 256] : l_idx[grow];
    }
    __syncthreads();
    for (int e = tid; e < 8 * 300; e += 256) {
        int rr = e / 300, t = e - rr * 300;
        xs[e] = emb[(long)sidx[rr] * 300 + t];
    }
    __syncthreads();
    int col = part * 256 + tid;
    float bias = b_ioux[col] + b_iouh[col];
    float acc[8];
#pragma unroll
    for (int r = 0; r < 8; r++) acc[r] = bias;
#pragma unroll 6
    for (int t = 0; t < 300; t++) {
        float w = g_WxT[t * 768 + col];
#pragma unroll
        for (int r = 0; r < 8; r++) acc[r] = fmaf(w, xs[r * 300 + t], acc[r]);
    }
#pragma unroll
    for (int r = 0; r < 8; r++) g_iou[(rowgrp * 8 + r) * 768 + col] = acc[r];
}

__device__ void st_leafgate(int bid, int tid) {
    for (int row = bid; row < 512; row += NBLK) {
        int side = row >> 8, leaf = row & 255;
        const float* base = &g_iou[row * 768];
        float iv = sigm(base[tid]);
        float ov = sigm(base[256 + tid]);
        float uv = tanhf(base[512 + tid]);
        float c = iv * uv;
        float h = ov * tanhf(c);
        g_c[side][leaf * 256 + tid] = c;
        g_mat[side][leaf * 256 + tid] = h;
    }
}

// ================= per-group stages (148 blocks, group g) =================

// split-K tree GEMM partials for group g
template <int RT>
__device__ void st_accumG(int gb, int tid, float* smf, int mode, int g, int lev) {
    int k = 256 >> lev, ES = c_ES[lev];
    int tg_cnt = k / RT;
    if (gb >= tg_cnt * ES) return;
    int tg = gb / ES, es_ = gb - tg * ES;
    int eNa = 256 / ES, e0 = es_ * eNa;
    int offp = c_off[lev - 1];
    int cnt = RT * 2 * eNa;
    const float* hsrc = mode ? g_hA[g] : g_mat[g];
    for (int t = tid; t < cnt; t += 256) {
        int r = t / (2 * eNa); int rem = t - r * 2 * eNa;
        int cc = rem / eNa; int e = rem - cc * eNa;
        int node = tg * RT + r;
        smf[t] = hsrc[(offp + 2 * node + cc) * 256 + e0 + e];
    }
    __syncthreads();
    float a0[RT], a1[RT], a2[RT], a3[RT], a4[RT];
#pragma unroll
    for (int r = 0; r < RT; r++) { a0[r] = a1[r] = a2[r] = a3[r] = a4[r] = 0.f; }
#pragma unroll 4
    for (int ee = 0; ee < eNa; ee++) {
        float4 w = g_Wpack[(e0 + ee) * 256 + tid];
#pragma unroll
        for (int r = 0; r < RT; r++) {
            float h0 = smf[r * 2 * eNa + ee], h1 = smf[r * 2 * eNa + eNa + ee];
            float hv = h0 + h1;
            a0[r] = fmaf(w.x, hv, a0[r]); a1[r] = fmaf(w.y, hv, a1[r]);
            a2[r] = fmaf(w.z, hv, a2[r]);
            a3[r] = fmaf(w.w, h0, a3[r]); a4[r] = fmaf(w.w, h1, a4[r]);
        }
    }
#pragma unroll
    for (int r = 0; r < RT; r++) {
        float* b = &g_treePart[g][((tg * RT + r) * ES + es_) * 1280];
        b[tid] = a0[r]; b[256 + tid] = a1[r]; b[512 + tid] = a2[r];
        b[768 + tid] = a3[r]; b[1024 + tid] = a4[r];
    }
}

__device__ void accumG_d(int gb, int tid, float* smf, int mode, int g, int lev) {
    int rt = c_RT[lev];
    if (rt == 8) st_accumG<8>(gb, tid, smf, mode, g, lev);
    else if (rt == 4) st_accumG<4>(gb, tid, smf, mode, g, lev);
    else if (rt == 2) st_accumG<2>(gb, tid, smf, mode, g, lev);
    else st_accumG<1>(gb, tid, smf, mode, g, lev);
}

// gate: reduce ES partials + LSTM cell; dohp => also hp = W1 @ h (attended deep levels)
__device__ void st_gateG(int gb, int tid, float* smf, int mode, int g, int lev, int dohp,
                         const float* __restrict__ bi, const float* __restrict__ bf) {
    int k = 256 >> lev, ES = c_ES[lev];
    if (gb >= k) return;
    int node = gb;
    int offp = c_off[lev - 1], offc = c_off[lev];
    float s0 = 0, s1 = 0, s2 = 0, s3 = 0, s4 = 0;
    for (int s = 0; s < ES; s++) {
        const float* b = &g_treePart[g][(node * ES + s) * 1280];
        s0 += __ldcg(b + tid);       s1 += __ldcg(b + 256 + tid);
        s2 += __ldcg(b + 512 + tid); s3 += __ldcg(b + 768 + tid);
        s4 += __ldcg(b + 1024 + tid);
    }
    float iv = sigm(s0 + bi[tid]), ov = sigm(s1 + bi[256 + tid]);
    float uv = tanhf(s2 + bi[512 + tid]);
    float f0 = sigm(s3 + bf[tid]), f1 = sigm(s4 + bf[tid]);
    const float* csrc = mode ? ((lev == 1) ? &g_c[1 - g][(2 * node) * 256]
                                           : &g_cA[g][(offp + 2 * node) * 256])
                             : &g_c[g][(offp + 2 * node) * 256];
    float c = iv * uv + f0 * csrc[tid] + f1 * csrc[256 + tid];
    float h = ov * tanhf(c);
    if (mode) { g_cA[g][(offc + node) * 256 + tid] = c; g_hPre[g][(offc + node) * 256 + tid] = h; }
    else      { g_c[g][(offc + node) * 256 + tid] = c;  g_mat[g][(offc + node) * 256 + tid] = h; }
    if (dohp) {
        float* hsm = smf; float* hpP = smf + 256;
        hsm[tid] = h;
        __syncthreads();
        int w = tid >> 5, lane = tid & 31;
        float a[8] = {0, 0, 0, 0, 0, 0, 0, 0};
        for (int ei = 0; ei < 32; ei++) {
            int e = w * 32 + ei; float hv = hsm[e];
#pragma unroll
            for (int c2 = 0; c2 < 8; c2++) a[c2] = fmaf(g_W1T[e * 256 + c2 * 32 + lane], hv, a[c2]);
        }
#pragma unroll
        for (int c2 = 0; c2 < 8; c2++) hpP[w * 256 + c2 * 32 + lane] = a[c2];
        __syncthreads();
        float s = 0;
#pragma unroll
        for (int w2 = 0; w2 < 8; w2++) s += hpP[w2 * 256 + tid];
        g_hp[g][node * 256 + tid] = s;
    }
}

// proj -> pbT[g] + colsum[g]
__device__ void st_projG(int gb, int tid, float* smf, int g, const float* __restrict__ ba) {
    if (gb < 128) {
        int mb = gb * 4;
        float* ms = smf;
#pragma unroll
        for (int r = 0; r < 4; r++) {
            int m = min(mb + r, 510);
            ms[r * 256 + tid] = g_mat[g][m * 256 + tid];
        }
        __syncthreads();
        float b0 = ba[tid]; float a0 = b0, a1 = b0, a2 = b0, a3 = b0;
#pragma unroll 8
        for (int e = 0; e < 256; e++) {
            float w = g_W2T[e * 256 + tid];
            a0 = fmaf(w, ms[e], a0);       a1 = fmaf(w, ms[256 + e], a1);
            a2 = fmaf(w, ms[512 + e], a2); a3 = fmaf(w, ms[768 + e], a3);
        }
        // thread = dim, 4 consecutive m: one vec store (m=511 garbage; excluded in softmax)
        *(float4*)&g_pbT[g][tid * 512 + mb] = make_float4(a0, a1, a2, a3);
    } else if (gb < 132) {
        int qc = gb - 128;
        int d = tid & 63, rs = tid >> 6, dim = qc * 64 + d;
        float a = 0;
        for (int m = rs; m < 511; m += 4) a += g_mat[g][m * 256 + dim];
        float* red = smf;
        red[rs * 64 + d] = a;
        __syncthreads();
        if (rs == 0) g_colsum[g][dim] = red[d] + red[64 + d] + red[128 + d] + red[192 + d];
    }
}

// fused attend (lev 0..3): hp + scores + softmax + combine; R rows/block
template <int R>
__device__ void st_attendF(int gb, int tid, float* smf, int g, int lev,
                           const float* __restrict__ Wa) {
    int rows = 256 >> lev;
    int rg = rows / R;
    if (gb >= rg) return;
    int nb = gb * R;
    int roff = c_off[lev];
    float* hsm = smf;                     // R*256
    float* wa  = hsm + R * 256;           // 256
    float* hpP = wa + 256;                // 8*R*256
    float* es  = hpP + 8 * R * 256;       // R*512
    float* red = es + R * 512;            // 16
    float4* sp = (float4*)(red + 16);     // 4*R*64 float4
    const float* hsrc = lev ? g_hPre[g] : g_mat[1 - g];
#pragma unroll
    for (int r = 0; r < R; r++) hsm[r * 256 + tid] = hsrc[(roff + nb + r) * 256 + tid];
    wa[tid] = Wa[tid];
    __syncthreads();
    int w = tid >> 5, lane = tid & 31;
    {
        float acc[R][8];
#pragma unroll
        for (int r = 0; r < R; r++)
#pragma unroll
            for (int c = 0; c < 8; c++) acc[r][c] = 0.f;
        for (int ei = 0; ei < 32; ei++) {
            int e = w * 32 + ei;
#pragma unroll
            for (int c = 0; c < 8; c++) {
                float w1 = g_W1T[e * 256 + c * 32 + lane];
#pragma unroll
                for (int r = 0; r < R; r++) acc[r][c] = fmaf(w1, hsm[r * 256 + e], acc[r][c]);
            }
        }
#pragma unroll
        for (int r = 0; r < R; r++)
#pragma unroll
            for (int c = 0; c < 8; c++) hpP[w * R * 256 + r * 256 + c * 32 + lane] = acc[r][c];
    }
    __syncthreads();
    float hpr[R];
#pragma unroll
    for (int r = 0; r < R; r++) {
        float s = 0;
#pragma unroll
        for (int w2 = 0; w2 < 8; w2++) s += hpP[w2 * R * 256 + r * 256 + tid];
        hpr[r] = s;
    }
    __syncthreads();
#pragma unroll
    for (int r = 0; r < R; r++) hpP[r * 256 + tid] = hpr[r];
    __syncthreads();
    float sa[R][2];
#pragma unroll
    for (int r = 0; r < R; r++) { sa[r][0] = 0.f; sa[r][1] = 0.f; }
    const float* pbb = g_pbT[g];
#pragma unroll 4
    for (int d = 0; d < 256; d++) {
        float pb0 = pbb[d * 512 + w * 32 + lane];
        float pb1 = pbb[d * 512 + 256 + w * 32 + lane];
        float wv = wa[d];
#pragma unroll
        for (int r = 0; r < R; r++) {
            float hv = hpP[r * 256 + d];
            sa[r][0] = fmaf(wv, tfast(hv + pb0), sa[r][0]);
            sa[r][1] = fmaf(wv, tfast(hv + pb1), sa[r][1]);
        }
    }
#pragma unroll
    for (int r = 0; r < R; r++) {
        es[r * 512 + w * 32 + lane] = sa[r][0];
        es[r * 512 + 256 + w * 32 + lane] = sa[r][1];
    }
    __syncthreads();
    float inv[R];
#pragma unroll
    for (int r = 0; r < R; r++) {
        float e0 = es[r * 512 + tid];
        float e1 = (tid < 255) ? es[r * 512 + 256 + tid] : -1e30f;
        float mx = blkmax(fmaxf(e0, e1), red, tid);
        float x0 = __expf(e0 - mx);
        float x1 = (tid < 255) ? __expf(e1 - mx) : 0.f;
        es[r * 512 + tid] = x0; es[r * 512 + 256 + tid] = x1;
        inv[r] = 1.0f / blksum(x0 + x1, red, tid);
    }
    __syncthreads();
    int q = tid & 63, st2 = tid >> 6;
    const float4* m4 = (const float4*)g_mat[g];
    float4 a2[R];
#pragma unroll
    for (int r = 0; r < R; r++) a2[r] = make_float4(0, 0, 0, 0);
#pragma unroll 8
    for (int m = st2; m < 511; m += 4) {
        float4 mv = m4[m * 64 + q];
#pragma unroll
        for (int r = 0; r < R; r++) {
            float e = es[r * 512 + m];
            a2[r].x = fmaf(e, mv.x, a2[r].x);
            a2[r].y = fmaf(e, mv.y, a2[r].y);
            a2[r].z = fmaf(e, mv.z, a2[r].z);
            a2[r].w = fmaf(e, mv.w, a2[r].w);
        }
    }
#pragma unroll
    for (int r = 0; r < R; r++) sp[(st2 * R + r) * 64 + q] = a2[r];
    __syncthreads();
    if (st2 == 0) {
        const float* cs = g_colsum[g];
#pragma unroll
        for (int r = 0; r < R; r++) {
            float4 t = sp[r * 64 + q];
            float4 b1 = sp[(R + r) * 64 + q], b2 = sp[(2 * R + r) * 64 + q], b3 = sp[(3 * R + r) * 64 + q];
            t.x += b1.x + b2.x + b3.x; t.y += b1.y + b2.y + b3.y;
            t.z += b1.z + b2.z + b3.z; t.w += b1.w + b2.w + b3.w;
            float* o = &g_hA[g][(roff + nb + r) * 256 + 4 * q];
            o[0] = cs[4 * q + 0] - t.x * inv[r] + hsm[r * 256 + 4 * q + 0];
            o[1] = cs[4 * q + 1] - t.y * inv[r] + hsm[r * 256 + 4 * q + 1];
            o[2] = cs[4 * q + 2] - t.z * inv[r] + hsm[r * 256 + 4 * q + 2];
            o[3] = cs[4 * q + 3] - t.w * inv[r] + hsm[r * 256 + 4 * q + 3];
        }
    }
}

// fused deep attend (lev 4..8): block per row, hp precomputed in gate
__device__ void st_attendD(int gb, int tid, float* smf, int g, int lev,
                           const float* __restrict__ Wa) {
    int k = 256 >> lev;
    if (gb >= k) return;
    int n = gb, grow = c_off[lev] + n;
    float* hp = smf; float* wa = hp + 256; float* es = wa + 256;
    float* red = es + 512; float* hr = red + 16;
    float4* sp = (float4*)(hr + 256);
    hp[tid] = __ldcg(&g_hp[g][n * 256 + tid]);
    wa[tid] = Wa[tid];
    hr[tid] = g_hPre[g][grow * 256 + tid];
    __syncthreads();
    int w = tid >> 5, lane = tid & 31;
    float s0 = 0.f, s1 = 0.f;
    const float* pbb = g_pbT[g];
#pragma unroll 4
    for (int d = 0; d < 256; d++) {
        float pb0 = pbb[d * 512 + w * 32 + lane];
        float pb1 = pbb[d * 512 + 256 + w * 32 + lane];
        float wv = wa[d], hv = hp[d];
        s0 = fmaf(wv, tfast(hv + pb0), s0);
        s1 = fmaf(wv, tfast(hv + pb1), s1);
    }
    es[w * 32 + lane] = s0; es[256 + w * 32 + lane] = s1;
    __syncthreads();
    float e0 = es[tid];
    float e1 = (tid < 255) ? es[256 + tid] : -1e30f;
    float mx = blkmax(fmaxf(e0, e1), red, tid);
    float x0 = __expf(e0 - mx), x1 = (tid < 255) ? __expf(e1 - mx) : 0.f;
    es[tid] = x0; es[256 + tid] = x1;
    float inv = 1.0f / blksum(x0 + x1, red, tid);
    __syncthreads();
    int q = tid & 63, st2 = tid >> 6;
    const float4* m4 = (const float4*)g_mat[g];
    float4 a = make_float4(0, 0, 0, 0);
#pragma unroll 8
    for (int m = st2; m < 511; m += 4) {
        float4 mv = m4[m * 64 + q]; float e = es[m];
        a.x = fmaf(e, mv.x, a.x); a.y = fmaf(e, mv.y, a.y);
        a.z = fmaf(e, mv.z, a.z); a.w = fmaf(e, mv.w, a.w);
    }
    sp[st2 * 64 + q] = a;
    __syncthreads();
    if (st2 == 0) {
        float4 t = sp[q], b1 = sp[64 + q], b2 = sp[128 + q], b3 = sp[192 + q];
        t.x += b1.x + b2.x + b3.x; t.y += b1.y + b2.y + b3.y;
        t.z += b1.z + b2.z + b3.z; t.w += b1.w + b2.w + b3.w;
        const float* cs = g_colsum[g];
        float* o = &g_hA[g][grow * 256 + 4 * q];
        o[0] = cs[4 * q + 0] - t.x * inv + hr[4 * q + 0];
        o[1] = cs[4 * q + 1] - t.y * inv + hr[4 * q + 1];
        o[2] = cs[4 * q + 2] - t.z * inv + hr[4 * q + 2];
        o[3] = cs[4 * q + 3] - t.w * inv + hr[4 * q + 3];
    }
}

__device__ void st_final(int tid, float* smf,
                         const float* __restrict__ W_wh, const float* __restrict__ b_wh,
                         const float* __restrict__ W_wp, const float* __restrict__ b_wp,
                         float* __restrict__ out) {
    float* v = smf; float* hid = smf + 512;
    float lh = tanhf(g_mat[0][510 * 256 + tid] + g_hA[1][510 * 256 + tid]);
    float rh = tanhf(g_hA[0][510 * 256 + tid] + g_mat[1][510 * 256 + tid]);
    v[tid] = lh * rh;
    v[256 + tid] = fabsf(lh - rh);
    __syncthreads();
    if (tid < 128) {
        float a = b_wh[tid];
        for (int e = 0; e < 512; e++) a = fmaf(W_wh[tid * 512 + e], v[e], a);
        hid[tid] = sigm(a);
    }
    __syncthreads();
    if (tid < 32) {
        float z[5];
#pragma unroll
        for (int c = 0; c < 5; c++) {
            float a = 0.f;
            for (int e = tid; e < 128; e += 32) a = fmaf(W_wp[c * 128 + e], hid[e], a);
#pragma unroll
            for (int o = 16; o; o >>= 1) a += __shfl_xor_sync(~0u, a, o);
            z[c] = a + b_wp[c];
        }
        if (tid == 0) {
            float mx = z[0];
#pragma unroll
            for (int c = 1; c < 5; c++) mx = fmaxf(mx, z[c]);
            float s = 0.f;
#pragma unroll
            for (int c = 0; c < 5; c++) s += expf(z[c] - mx);
            float ls = logf(s);
#pragma unroll
            for (int c = 0; c < 5; c++) out[c] = z[c] - mx - ls;
        }
    }
}

// ================= persistent mega kernel =================
__global__ void __launch_bounds__(256, 2)
mega_kernel(const int* l_idx, const int* r_idx, const float* emb,
            const float* W_ioux, const float* b_ioux,
            const float* W_iouh, const float* b_iouh,
            const float* W_fh, const float* b_fh,
            const float* Wa, const float* b_attnh,
            const float* W_wh, const float* b_wh,
            const float* W_wp, const float* b_wp,
            const float* W_attnh, float* out) {
    __shared__ __align__(16) float smf[11600];
    int bid = blockIdx.x, tid = threadIdx.x;
    int g = bid >= GBLK;
    int gb = bid - g * GBLK;

    st_prep(bid, tid, W_ioux, W_iouh, W_fh, W_attnh);               gbarG(0);
    st_leafgemm(bid, tid, smf, l_idx, r_idx, emb, b_ioux, b_iouh);  gbarG(1);
    st_leafgate(bid, tid);                                          gbarG(2);

    int b = 0;
    // no-attn tree (side g)
    for (int lev = 1; lev <= 8; lev++) {
        accumG_d(gb, tid, smf, 0, g, lev);                    gbarL(g, b++);
        st_gateG(gb, tid, smf, 0, g, lev, 0, b_iouh, b_fh);   gbarL(g, b++);
    }

    st_projG(gb, tid, smf, g, b_attnh);                       gbarL(g, b++);
    st_attendF<2>(gb, tid, smf, g, 0, Wa);                    gbarL(g, b++);

    for (int lev = 1; lev <= 3; lev++) {
        accumG_d(gb, tid, smf, 1, g, lev);                    gbarL(g, b++);
        st_gateG(gb, tid, smf, 1, g, lev, 0, b_iouh, b_fh);   gbarL(g, b++);
        st_attendF<1>(gb, tid, smf, g, lev, Wa);              gbarL(g, b++);
    }
    for (int lev = 4; lev <= 8; lev++) {
        accumG_d(gb, tid, smf, 1, g, lev);                    gbarL(g, b++);
        st_gateG(gb, tid, smf, 1, g, lev, 1, b_iouh, b_fh);   gbarL(g, b++);
        st_attendD(gb, tid, smf, g, lev, Wa);                 gbarL(g, b++);
    }

    gbarG(3);
    if (bid == 0) st_final(tid, smf, W_wh, b_wh, W_wp, b_wp, out);
}

// ================= host =================
extern "C" void kernel_launch(void* const* d_in, const int* in_sizes, int n_in,
                              void* d_out, int out_size) {
    const int*   l_idx   = (const int*)d_in[0];
    const int*   r_idx   = (const int*)d_in[1];
    const float* emb     = (const float*)d_in[2];
    const float* W_ioux  = (const float*)d_in[3];
    const float* b_ioux  = (const float*)d_in[4];
    const float* W_iouh  = (const float*)d_in[5];
    const float* b_iouh  = (const float*)d_in[6];
    // d_in[7]=W_fx, d_in[8]=b_fx unused by reference
    const float* W_fh    = (const float*)d_in[9];
    const float* b_fh    = (const float*)d_in[10];
    const float* Wa      = (const float*)d_in[11];
    const float* W_attnh = (const float*)d_in[12];
    const float* b_attnh = (const float*)d_in[13];
    const float* W_wh    = (const float*)d_in[14];
    const float* b_wh    = (const float*)d_in[15];
    const float* W_wp    = (const float*)d_in[16];
    const float* b_wp    = (const float*)d_in[17];
    float* out = (float*)d_out;

    reset_kernel<<<1, 128>>>();
    mega_kernel<<<NBLK, 256>>>(l_idx, r_idx, emb,
                               W_ioux, b_ioux, W_iouh, b_iouh, W_fh, b_fh,
                               Wa, b_attnh, W_wh, b_wh, W_wp, b_wp,
                               W_attnh, out);
}

// round 7
// speedup vs baseline: 1.2089x; 1.0006x over previous
#include <cuda_runtime.h>
#include <math.h>

#define NBLK 296
#define GBLK 148
#define MTOT 511

// ---------------- device scratch ----------------
__device__ float  g_WxT[300 * 768];
__device__ float4 g_Wpack[65536];            // {Wh_i,Wh_o,Wh_u,Wf}[e][j]
__device__ float  g_W1T[65536];              // W_attnh[:, :256]^T [e][d]
__device__ float  g_W2T[65536];              // W_attnh[:, 256:]^T [e][d]
__device__ float  g_iou[512 * 768];
__device__ float  g_mat[2][MTOT * 256];
__device__ float  g_c[2][MTOT * 256];
__device__ float  g_hA[2][MTOT * 256];
__device__ float  g_cA[2][MTOT * 256];
__device__ float  g_hPre[2][MTOT * 256];
__device__ float  g_pbT[2][256 * 512];       // transposed proj+bias: [d][m]
__device__ float  g_colsum[2][256];
__device__ float  g_hp[2][16 * 256];
__device__ float  g_treePart[2][1024 * 1280];
__device__ int    g_barG[8];
__device__ int    g_barL[2][48];

__constant__ int c_off[9] = {0, 256, 384, 448, 480, 496, 504, 508, 510};
__constant__ int c_RT[9]  = {0, 8, 8, 8, 8, 8, 4, 2, 1};
__constant__ int c_ES[9]  = {0, 8, 16, 32, 32, 16, 16, 16, 16};

__device__ __forceinline__ float sigm(float x) { return 1.0f / (1.0f + expf(-x)); }
__device__ __forceinline__ float tfast(float x) {
    float y; asm("tanh.approx.f32 %0,%1;" : "=f"(y) : "f"(x)); return y;
}

// ---------------- barriers ----------------
__device__ __forceinline__ void gbarG(int id) {
    __syncthreads();
    if (threadIdx.x == 0) {
        __threadfence();
        atomicAdd(&g_barG[id], 1);
        while (((volatile int*)g_barG)[id] < NBLK) __nanosleep(64);
        __threadfence();
    }
    __syncthreads();
}
__device__ __forceinline__ void gbarL(int g, int id) {
    __syncthreads();
    if (threadIdx.x == 0) {
        __threadfence();
        atomicAdd(&g_barL[g][id], 1);
        while (((volatile int*)g_barL[g])[id] < GBLK) __nanosleep(64);
        __threadfence();
    }
    __syncthreads();
}

__global__ void reset_kernel() {
    if (threadIdx.x < 8) g_barG[threadIdx.x] = 0;
    if (threadIdx.x < 96) g_barL[threadIdx.x / 48][threadIdx.x % 48] = 0;
}

// ---------------- block reductions ----------------
__device__ __forceinline__ float blkmax(float v, float* red, int tid) {
    for (int o = 16; o; o >>= 1) v = fmaxf(v, __shfl_xor_sync(~0u, v, o));
    if ((tid & 31) == 0) red[tid >> 5] = v;
    __syncthreads();
    if (tid == 0) { float m = red[0]; for (int i = 1; i < 8; i++) m = fmaxf(m, red[i]); red[8] = m; }
    __syncthreads();
    float r = red[8]; __syncthreads(); return r;
}
__device__ __forceinline__ float blksum(float v, float* red, int tid) {
    for (int o = 16; o; o >>= 1) v += __shfl_xor_sync(~0u, v, o);
    if ((tid & 31) == 0) red[tid >> 5] = v;
    __syncthreads();
    if (tid == 0) { float s = 0; for (int i = 0; i < 8; i++) s += red[i]; red[8] = s; }
    __syncthreads();
    float r = red[8]; __syncthreads(); return r;
}

// ================= shared stages (all 296 blocks) =================

__device__ void st_prep(int bid, int tid,
                        const float* __restrict__ W_ioux, const float* __restrict__ W_iouh,
                        const float* __restrict__ W_fh,   const float* __restrict__ W_attnh) {
    const int N1 = 300 * 768, N2 = 65536, N3 = 65536, N4 = 65536;
    for (int i = bid * 256 + tid; i < N1 + N2 + N3 + N4; i += NBLK * 256) {
        if (i < N1) {
            int t = i / 768, j = i - t * 768;
            g_WxT[i] = W_ioux[j * 300 + t];
        } else if (i < N1 + N2) {
            int e = i - N1; int t = e >> 8, j = e & 255;
            g_Wpack[e] = make_float4(W_iouh[j * 256 + t], W_iouh[(256 + j) * 256 + t],
                                     W_iouh[(512 + j) * 256 + t], W_fh[j * 256 + t]);
        } else if (i < N1 + N2 + N3) {
            int e = i - N1 - N2; int ee = e >> 8, d = e & 255;
            g_W1T[e] = W_attnh[d * 512 + ee];
        } else {
            int e = i - N1 - N2 - N3; int ee = e >> 8, d = e & 255;
            g_W2T[e] = W_attnh[d * 512 + 256 + ee];
        }
    }
}

__device__ void st_leafgemm(int bid, int tid, float* smf,
                            const int* __restrict__ l_idx, const int* __restrict__ r_idx,
                            const float* __restrict__ emb,
                            const float* __restrict__ b_ioux, const float* __restrict__ b_iouh) {
    if (bid >= 192) return;
    float* xs = smf;
    int* sidx = (int*)(smf + 2400);
    int rowgrp = bid & 63, part = bid >> 6;
    if (tid < 8) {
        int grow = rowgrp * 8 + tid;
        sidx[tid] = (grow >= 256) ? r_idx[grow - 256] : l_idx[grow];
    }
    __syncthreads();
    for (int e = tid; e < 8 * 300; e += 256) {
        int rr = e / 300, t = e - rr * 300;
        xs[e] = emb[(long)sidx[rr] * 300 + t];
    }
    __syncthreads();
    int col = part * 256 + tid;
    float bias = b_ioux[col] + b_iouh[col];
    float acc[8];
#pragma unroll
    for (int r = 0; r < 8; r++) acc[r] = bias;
#pragma unroll 6
    for (int t = 0; t < 300; t++) {
        float w = g_WxT[t * 768 + col];
#pragma unroll
        for (int r = 0; r < 8; r++) acc[r] = fmaf(w, xs[r * 300 + t], acc[r]);
    }
#pragma unroll
    for (int r = 0; r < 8; r++) g_iou[(rowgrp * 8 + r) * 768 + col] = acc[r];
}

__device__ void st_leafgate(int bid, int tid) {
    for (int row = bid; row < 512; row += NBLK) {
        int side = row >> 8, leaf = row & 255;
        const float* base = &g_iou[row * 768];
        float iv = sigm(base[tid]);
        float ov = sigm(base[256 + tid]);
        float uv = tanhf(base[512 + tid]);
        float c = iv * uv;
        float h = ov * tanhf(c);
        g_c[side][leaf * 256 + tid] = c;
        g_mat[side][leaf * 256 + tid] = h;
    }
}

// ================= per-group stages (148 blocks, group g) =================

// split-K tree GEMM partials for group g
template <int RT>
__device__ void st_accumG(int gb, int tid, float* smf, int mode, int g, int lev) {
    int k = 256 >> lev, ES = c_ES[lev];
    int tg_cnt = k / RT;
    if (gb >= tg_cnt * ES) return;
    int tg = gb / ES, es_ = gb - tg * ES;
    int eNa = 256 / ES, e0 = es_ * eNa;
    int offp = c_off[lev - 1];
    int cnt = RT * 2 * eNa;
    const float* hsrc = mode ? g_hA[g] : g_mat[g];
    for (int t = tid; t < cnt; t += 256) {
        int r = t / (2 * eNa); int rem = t - r * 2 * eNa;
        int cc = rem / eNa; int e = rem - cc * eNa;
        int node = tg * RT + r;
        smf[t] = hsrc[(offp + 2 * node + cc) * 256 + e0 + e];
    }
    __syncthreads();
    float a0[RT], a1[RT], a2[RT], a3[RT], a4[RT];
#pragma unroll
    for (int r = 0; r < RT; r++) { a0[r] = a1[r] = a2[r] = a3[r] = a4[r] = 0.f; }
#pragma unroll 4
    for (int ee = 0; ee < eNa; ee++) {
        float4 w = g_Wpack[(e0 + ee) * 256 + tid];
#pragma unroll
        for (int r = 0; r < RT; r++) {
            float h0 = smf[r * 2 * eNa + ee], h1 = smf[r * 2 * eNa + eNa + ee];
            float hv = h0 + h1;
            a0[r] = fmaf(w.x, hv, a0[r]); a1[r] = fmaf(w.y, hv, a1[r]);
            a2[r] = fmaf(w.z, hv, a2[r]);
            a3[r] = fmaf(w.w, h0, a3[r]); a4[r] = fmaf(w.w, h1, a4[r]);
        }
    }
#pragma unroll
    for (int r = 0; r < RT; r++) {
        float* b = &g_treePart[g][((tg * RT + r) * ES + es_) * 1280];
        b[tid] = a0[r]; b[256 + tid] = a1[r]; b[512 + tid] = a2[r];
        b[768 + tid] = a3[r]; b[1024 + tid] = a4[r];
    }
}

__device__ void accumG_d(int gb, int tid, float* smf, int mode, int g, int lev) {
    int rt = c_RT[lev];
    if (rt == 8) st_accumG<8>(gb, tid, smf, mode, g, lev);
    else if (rt == 4) st_accumG<4>(gb, tid, smf, mode, g, lev);
    else if (rt == 2) st_accumG<2>(gb, tid, smf, mode, g, lev);
    else st_accumG<1>(gb, tid, smf, mode, g, lev);
}

// gate: reduce ES partials + LSTM cell; dohp => also hp = W1 @ h (attended deep levels)
__device__ void st_gateG(int gb, int tid, float* smf, int mode, int g, int lev, int dohp,
                         const float* __restrict__ bi, const float* __restrict__ bf) {
    int k = 256 >> lev, ES = c_ES[lev];
    if (gb >= k) return;
    int node = gb;
    int offp = c_off[lev - 1], offc = c_off[lev];
    float s0 = 0, s1 = 0, s2 = 0, s3 = 0, s4 = 0;
    for (int s = 0; s < ES; s++) {
        const float* b = &g_treePart[g][(node * ES + s) * 1280];
        s0 += __ldcg(b + tid);       s1 += __ldcg(b + 256 + tid);
        s2 += __ldcg(b + 512 + tid); s3 += __ldcg(b + 768 + tid);
        s4 += __ldcg(b + 1024 + tid);
    }
    float iv = sigm(s0 + bi[tid]), ov = sigm(s1 + bi[256 + tid]);
    float uv = tanhf(s2 + bi[512 + tid]);
    float f0 = sigm(s3 + bf[tid]), f1 = sigm(s4 + bf[tid]);
    const float* csrc = mode ? ((lev == 1) ? &g_c[1 - g][(2 * node) * 256]
                                           : &g_cA[g][(offp + 2 * node) * 256])
                             : &g_c[g][(offp + 2 * node) * 256];
    float c = iv * uv + f0 * csrc[tid] + f1 * csrc[256 + tid];
    float h = ov * tanhf(c);
    if (mode) { g_cA[g][(offc + node) * 256 + tid] = c; g_hPre[g][(offc + node) * 256 + tid] = h; }
    else      { g_c[g][(offc + node) * 256 + tid] = c;  g_mat[g][(offc + node) * 256 + tid] = h; }
    if (dohp) {
        float* hsm = smf; float* hpP = smf + 256;
        hsm[tid] = h;
        __syncthreads();
        int w = tid >> 5, lane = tid & 31;
        float a[8] = {0, 0, 0, 0, 0, 0, 0, 0};
        for (int ei = 0; ei < 32; ei++) {
            int e = w * 32 + ei; float hv = hsm[e];
#pragma unroll
            for (int c2 = 0; c2 < 8; c2++) a[c2] = fmaf(g_W1T[e * 256 + c2 * 32 + lane], hv, a[c2]);
        }
#pragma unroll
        for (int c2 = 0; c2 < 8; c2++) hpP[w * 256 + c2 * 32 + lane] = a[c2];
        __syncthreads();
        float s = 0;
#pragma unroll
        for (int w2 = 0; w2 < 8; w2++) s += hpP[w2 * 256 + tid];
        g_hp[g][node * 256 + tid] = s;
    }
}

// proj -> pbT[g] + colsum[g]
__device__ void st_projG(int gb, int tid, float* smf, int g, const float* __restrict__ ba) {
    if (gb < 128) {
        int mb = gb * 4;
        float* ms = smf;
#pragma unroll
        for (int r = 0; r < 4; r++) {
            int m = min(mb + r, 510);
            ms[r * 256 + tid] = g_mat[g][m * 256 + tid];
        }
        __syncthreads();
        float b0 = ba[tid]; float a0 = b0, a1 = b0, a2 = b0, a3 = b0;
#pragma unroll 8
        for (int e = 0; e < 256; e++) {
            float w = g_W2T[e * 256 + tid];
            a0 = fmaf(w, ms[e], a0);       a1 = fmaf(w, ms[256 + e], a1);
            a2 = fmaf(w, ms[512 + e], a2); a3 = fmaf(w, ms[768 + e], a3);
        }
        // thread = dim, 4 consecutive m: one vec store (m=511 garbage; excluded in softmax)
        *(float4*)&g_pbT[g][tid * 512 + mb] = make_float4(a0, a1, a2, a3);
    } else if (gb < 132) {
        int qc = gb - 128;
        int d = tid & 63, rs = tid >> 6, dim = qc * 64 + d;
        float a = 0;
        for (int m = rs; m < 511; m += 4) a += g_mat[g][m * 256 + dim];
        float* red = smf;
        red[rs * 64 + d] = a;
        __syncthreads();
        if (rs == 0) g_colsum[g][dim] = red[d] + red[64 + d] + red[128 + d] + red[192 + d];
    }
}

// fused attend (lev 0..3): hp + scores + softmax + combine; R rows/block
template <int R>
__device__ void st_attendF(int gb, int tid, float* smf, int g, int lev,
                           const float* __restrict__ Wa) {
    int rows = 256 >> lev;
    int rg = rows / R;
    if (gb >= rg) return;
    int nb = gb * R;
    int roff = c_off[lev];
    float* hsm = smf;                     // R*256
    float* wa  = hsm + R * 256;           // 256
    float* hpP = wa + 256;                // 8*R*256
    float* es  = hpP + 8 * R * 256;       // R*512
    float* red = es + R * 512;            // 16
    float4* sp = (float4*)(red + 16);     // 4*R*64 float4
    const float* hsrc = lev ? g_hPre[g] : g_mat[1 - g];
#pragma unroll
    for (int r = 0; r < R; r++) hsm[r * 256 + tid] = hsrc[(roff + nb + r) * 256 + tid];
    wa[tid] = Wa[tid];
    __syncthreads();
    int w = tid >> 5, lane = tid & 31;
    {
        float acc[R][8];
#pragma unroll
        for (int r = 0; r < R; r++)
#pragma unroll
            for (int c = 0; c < 8; c++) acc[r][c] = 0.f;
        for (int ei = 0; ei < 32; ei++) {
            int e = w * 32 + ei;
#pragma unroll
            for (int c = 0; c < 8; c++) {
                float w1 = g_W1T[e * 256 + c * 32 + lane];
#pragma unroll
                for (int r = 0; r < R; r++) acc[r][c] = fmaf(w1, hsm[r * 256 + e], acc[r][c]);
            }
        }
#pragma unroll
        for (int r = 0; r < R; r++)
#pragma unroll
            for (int c = 0; c < 8; c++) hpP[w * R * 256 + r * 256 + c * 32 + lane] = acc[r][c];
    }
    __syncthreads();
    float hpr[R];
#pragma unroll
    for (int r = 0; r < R; r++) {
        float s = 0;
#pragma unroll
        for (int w2 = 0; w2 < 8; w2++) s += hpP[w2 * R * 256 + r * 256 + tid];
        hpr[r] = s;
    }
    __syncthreads();
#pragma unroll
    for (int r = 0; r < R; r++) hpP[r * 256 + tid] = hpr[r];
    __syncthreads();
    float sa[R][2];
#pragma unroll
    for (int r = 0; r < R; r++) { sa[r][0] = 0.f; sa[r][1] = 0.f; }
    const float* pbb = g_pbT[g];
#pragma unroll 4
    for (int d = 0; d < 256; d++) {
        float pb0 = pbb[d * 512 + w * 32 + lane];
        float pb1 = pbb[d * 512 + 256 + w * 32 + lane];
        float wv = wa[d];
#pragma unroll
        for (int r = 0; r < R; r++) {
            float hv = hpP[r * 256 + d];
            sa[r][0] = fmaf(wv, tfast(hv + pb0), sa[r][0]);
            sa[r][1] = fmaf(wv, tfast(hv + pb1), sa[r][1]);
        }
    }
#pragma unroll
    for (int r = 0; r < R; r++) {
        es[r * 512 + w * 32 + lane] = sa[r][0];
        es[r * 512 + 256 + w * 32 + lane] = sa[r][1];
    }
    __syncthreads();
    float inv[R];
#pragma unroll
    for (int r = 0; r < R; r++) {
        float e0 = es[r * 512 + tid];
        float e1 = (tid < 255) ? es[r * 512 + 256 + tid] : -1e30f;
        float mx = blkmax(fmaxf(e0, e1), red, tid);
        float x0 = __expf(e0 - mx);
        float x1 = (tid < 255) ? __expf(e1 - mx) : 0.f;
        es[r * 512 + tid] = x0; es[r * 512 + 256 + tid] = x1;
        inv[r] = 1.0f / blksum(x0 + x1, red, tid);
    }
    __syncthreads();
    int q = tid & 63, st2 = tid >> 6;
    const float4* m4 = (const float4*)g_mat[g];
    float4 a2[R];
#pragma unroll
    for (int r = 0; r < R; r++) a2[r] = make_float4(0, 0, 0, 0);
#pragma unroll 8
    for (int m = st2; m < 511; m += 4) {
        float4 mv = m4[m * 64 + q];
#pragma unroll
        for (int r = 0; r < R; r++) {
            float e = es[r * 512 + m];
            a2[r].x = fmaf(e, mv.x, a2[r].x);
            a2[r].y = fmaf(e, mv.y, a2[r].y);
            a2[r].z = fmaf(e, mv.z, a2[r].z);
            a2[r].w = fmaf(e, mv.w, a2[r].w);
        }
    }
#pragma unroll
    for (int r = 0; r < R; r++) sp[(st2 * R + r) * 64 + q] = a2[r];
    __syncthreads();
    if (st2 == 0) {
        const float* cs = g_colsum[g];
#pragma unroll
        for (int r = 0; r < R; r++) {
            float4 t = sp[r * 64 + q];
            float4 b1 = sp[(R + r) * 64 + q], b2 = sp[(2 * R + r) * 64 + q], b3 = sp[(3 * R + r) * 64 + q];
            t.x += b1.x + b2.x + b3.x; t.y += b1.y + b2.y + b3.y;
            t.z += b1.z + b2.z + b3.z; t.w += b1.w + b2.w + b3.w;
            float* o = &g_hA[g][(roff + nb + r) * 256 + 4 * q];
            o[0] = cs[4 * q + 0] - t.x * inv[r] + hsm[r * 256 + 4 * q + 0];
            o[1] = cs[4 * q + 1] - t.y * inv[r] + hsm[r * 256 + 4 * q + 1];
            o[2] = cs[4 * q + 2] - t.z * inv[r] + hsm[r * 256 + 4 * q + 2];
            o[3] = cs[4 * q + 3] - t.w * inv[r] + hsm[r * 256 + 4 * q + 3];
        }
    }
}

// fused deep attend (lev 4..8): block per row, hp precomputed in gate
__device__ void st_attendD(int gb, int tid, float* smf, int g, int lev,
                           const float* __restrict__ Wa) {
    int k = 256 >> lev;
    if (gb >= k) return;
    int n = gb, grow = c_off[lev] + n;
    float* hp = smf; float* wa = hp + 256; float* es = wa + 256;
    float* red = es + 512; float* hr = red + 16;
    float4* sp = (float4*)(hr + 256);
    hp[tid] = __ldcg(&g_hp[g][n * 256 + tid]);
    wa[tid] = Wa[tid];
    hr[tid] = g_hPre[g][grow * 256 + tid];
    __syncthreads();
    int w = tid >> 5, lane = tid & 31;
    float s0 = 0.f, s1 = 0.f;
    const float* pbb = g_pbT[g];
#pragma unroll 4
    for (int d = 0; d < 256; d++) {
        float pb0 = pbb[d * 512 + w * 32 + lane];
        float pb1 = pbb[d * 512 + 256 + w * 32 + lane];
        float wv = wa[d], hv = hp[d];
        s0 = fmaf(wv, tfast(hv + pb0), s0);
        s1 = fmaf(wv, tfast(hv + pb1), s1);
    }
    es[w * 32 + lane] = s0; es[256 + w * 32 + lane] = s1;
    __syncthreads();
    float e0 = es[tid];
    float e1 = (tid < 255) ? es[256 + tid] : -1e30f;
    float mx = blkmax(fmaxf(e0, e1), red, tid);
    float x0 = __expf(e0 - mx), x1 = (tid < 255) ? __expf(e1 - mx) : 0.f;
    es[tid] = x0; es[256 + tid] = x1;
    float inv = 1.0f / blksum(x0 + x1, red, tid);
    __syncthreads();
    int q = tid & 63, st2 = tid >> 6;
    const float4* m4 = (const float4*)g_mat[g];
    float4 a = make_float4(0, 0, 0, 0);
#pragma unroll 8
    for (int m = st2; m < 511; m += 4) {
        float4 mv = m4[m * 64 + q]; float e = es[m];
        a.x = fmaf(e, mv.x, a.x); a.y = fmaf(e, mv.y, a.y);
        a.z = fmaf(e, mv.z, a.z); a.w = fmaf(e, mv.w, a.w);
    }
    sp[st2 * 64 + q] = a;
    __syncthreads();
    if (st2 == 0) {
        float4 t = sp[q], b1 = sp[64 + q], b2 = sp[128 + q], b3 = sp[192 + q];
        t.x += b1.x + b2.x + b3.x; t.y += b1.y + b2.y + b3.y;
        t.z += b1.z + b2.z + b3.z; t.w += b1.w + b2.w + b3.w;
        const float* cs = g_colsum[g];
        float* o = &g_hA[g][grow * 256 + 4 * q];
        o[0] = cs[4 * q + 0] - t.x * inv + hr[4 * q + 0];
        o[1] = cs[4 * q + 1] - t.y * inv + hr[4 * q + 1];
        o[2] = cs[4 * q + 2] - t.z * inv + hr[4 * q + 2];
        o[3] = cs[4 * q + 3] - t.w * inv + hr[4 * q + 3];
    }
}

__device__ void st_final(int tid, float* smf,
                         const float* __restrict__ W_wh, const float* __restrict__ b_wh,
                         const float* __restrict__ W_wp, const float* __restrict__ b_wp,
                         float* __restrict__ out) {
    float* v = smf; float* hid = smf + 512;
    float lh = tanhf(g_mat[0][510 * 256 + tid] + g_hA[1][510 * 256 + tid]);
    float rh = tanhf(g_hA[0][510 * 256 + tid] + g_mat[1][510 * 256 + tid]);
    v[tid] = lh * rh;
    v[256 + tid] = fabsf(lh - rh);
    __syncthreads();
    if (tid < 128) {
        float a = b_wh[tid];
        for (int e = 0; e < 512; e++) a = fmaf(W_wh[tid * 512 + e], v[e], a);
        hid[tid] = sigm(a);
    }
    __syncthreads();
    if (tid < 32) {
        float z[5];
#pragma unroll
        for (int c = 0; c < 5; c++) {
            float a = 0.f;
            for (int e = tid; e < 128; e += 32) a = fmaf(W_wp[c * 128 + e], hid[e], a);
#pragma unroll
            for (int o = 16; o; o >>= 1) a += __shfl_xor_sync(~0u, a, o);
            z[c] = a + b_wp[c];
        }
        if (tid == 0) {
            float mx = z[0];
#pragma unroll
            for (int c = 1; c < 5; c++) mx = fmaxf(mx, z[c]);
            float s = 0.f;
#pragma unroll
            for (int c = 0; c < 5; c++) s += expf(z[c] - mx);
            float ls = logf(s);
#pragma unroll
            for (int c = 0; c < 5; c++) out[c] = z[c] - mx - ls;
        }
    }
}

// ================= persistent mega kernel =================
__global__ void __launch_bounds__(256, 2)
mega_kernel(const int* l_idx, const int* r_idx, const float* emb,
            const float* W_ioux, const float* b_ioux,
            const float* W_iouh, const float* b_iouh,
            const float* W_fh, const float* b_fh,
            const float* Wa, const float* b_attnh,
            const float* W_wh, const float* b_wh,
            const float* W_wp, const float* b_wp,
            const float* W_attnh, float* out) {
    __shared__ __align__(16) float smf[11600];
    int bid = blockIdx.x, tid = threadIdx.x;
    int g = bid >= GBLK;
    int gb = bid - g * GBLK;

    st_prep(bid, tid, W_ioux, W_iouh, W_fh, W_attnh);               gbarG(0);
    st_leafgemm(bid, tid, smf, l_idx, r_idx, emb, b_ioux, b_iouh);  gbarG(1);
    st_leafgate(bid, tid);                                          gbarG(2);

    int b = 0;
    // no-attn tree (side g)
    for (int lev = 1; lev <= 8; lev++) {
        accumG_d(gb, tid, smf, 0, g, lev);                    gbarL(g, b++);
        st_gateG(gb, tid, smf, 0, g, lev, 0, b_iouh, b_fh);   gbarL(g, b++);
    }

    st_projG(gb, tid, smf, g, b_attnh);                       gbarL(g, b++);
    st_attendF<2>(gb, tid, smf, g, 0, Wa);                    gbarL(g, b++);

    for (int lev = 1; lev <= 3; lev++) {
        accumG_d(gb, tid, smf, 1, g, lev);                    gbarL(g, b++);
        st_gateG(gb, tid, smf, 1, g, lev, 0, b_iouh, b_fh);   gbarL(g, b++);
        st_attendF<1>(gb, tid, smf, g, lev, Wa);              gbarL(g, b++);
    }
    for (int lev = 4; lev <= 8; lev++) {
        accumG_d(gb, tid, smf, 1, g, lev);                    gbarL(g, b++);
        st_gateG(gb, tid, smf, 1, g, lev, 1, b_iouh, b_fh);   gbarL(g, b++);
        st_attendD(gb, tid, smf, g, lev, Wa);                 gbarL(g, b++);
    }

    gbarG(3);
    if (bid == 0) st_final(tid, smf, W_wh, b_wh, W_wp, b_wp, out);
}

// ================= host =================
extern "C" void kernel_launch(void* const* d_in, const int* in_sizes, int n_in,
                              void* d_out, int out_size) {
    const int*   l_idx   = (const int*)d_in[0];
    const int*   r_idx   = (const int*)d_in[1];
    const float* emb     = (const float*)d_in[2];
    const float* W_ioux  = (const float*)d_in[3];
    const float* b_ioux  = (const float*)d_in[4];
    const float* W_iouh  = (const float*)d_in[5];
    const float* b_iouh  = (const float*)d_in[6];
    // d_in[7]=W_fx, d_in[8]=b_fx unused by reference
    const float* W_fh    = (const float*)d_in[9];
    const float* b_fh    = (const float*)d_in[10];
    const float* Wa      = (const float*)d_in[11];
    const float* W_attnh = (const float*)d_in[12];
    const float* b_attnh = (const float*)d_in[13];
    const float* W_wh    = (const float*)d_in[14];
    const float* b_wh    = (const float*)d_in[15];
    const float* W_wp    = (const float*)d_in[16];
    const float* b_wp    = (const float*)d_in[17];
    float* out = (float*)d_out;

    reset_kernel<<<1, 128>>>();
    mega_kernel<<<NBLK, 256>>>(l_idx, r_idx, emb,
                               W_ioux, b_ioux, W_iouh, b_iouh, W_fh, b_fh,
                               Wa, b_attnh, W_wh, b_wh, W_wp, b_wp,
                               W_attnh, out);
}